// round 6
// baseline (speedup 1.0000x reference)
#include <cuda_runtime.h>
#include <cuda_fp16.h>
#include <math.h>
#include <stdint.h>

// ---------------- problem constants ----------------
#define B_ 256
#define S_ 14
#define C_ 2513
#define SB 3584          // S_*B_
#define BH 262144        // B_*H_
#define G4 4096          // 4*H_
#define NSM 152

// ---------------- fp16 mma GEMM config ----------------
// CTA tile 128x256, 8 warps (2m x 4n), warp tile 64x64, K-chunk 32, 4-stage cp.async.
#define A_ST 4096                 // 128*32 halves
#define B_ST 8192                 // 256*32 halves
#define SLOT (A_ST + B_ST)        // 12288 halves = 24KB
#define NST  4
#define MAIN_H (NST * SLOT)       // 49152 halves = 96KB
#define SMEM_LSTM ((MAIN_H + 128 * 64) * 2)   // + h tile 16KB = 114688 B
#define SMEM_LIN  (MAIN_H * 2 + 1024)         // + bias 256 floats = 99328 B

// unroll DAG totals
#define NSTEP 15
#define TOT_TILES 3808            // sum_j 32*nact_j, nact_j=min(14,15-j)

// ---------------- scratch (device globals) ----------------
__device__ __half g_xT [SB * 1024];
__device__ float  g_xg_r[(size_t)SB * G4];
__device__ float  g_xg_u[(size_t)SB * G4];
__device__ float  g_hs [SB * 1024];
__device__ float  g_cs [SB * 1024];
__device__ __half g_hu [2 * SB * 1024];
__device__ float  g_cu [SB * 1024];
__device__ __half g_hn [SB * 1024];
__device__ __half g_wihr[(size_t)G4 * 1024];
__device__ __half g_wihu[(size_t)G4 * 1024];
__device__ __half g_whhu[(size_t)G4 * 1024];
__device__ __half g_wc [(size_t)2560 * 1024];
__device__ int    g_work;
__device__ int    g_cnt[NSTEP * 28];

__device__ __forceinline__ float sigf(float x) { return 1.0f / (1.0f + expf(-x)); }

// logical-k permutation within each 32-k block
__device__ __forceinline__ int perm_l(int p) {
    int b = (p >> 2) & 1, t = p >> 3, j = p & 3;
    return b * 16 + ((j < 2) ? (2 * t + j) : (2 * t + 8 + (j - 2)));
}
__device__ __forceinline__ int inv_l(int l) {
    int b = l >> 4, r = l & 15, hi = r >> 3, t = (r >> 1) & 3, e = r & 1;
    return t * 8 + b * 4 + hi * 2 + e;
}

// ---------------- low-level helpers ----------------
__device__ __forceinline__ uint32_t smaddr(const void* p) {
    uint32_t a;
    asm("{ .reg .u64 t; cvta.to.shared.u64 t, %1; cvt.u32.u64 %0, t; }" : "=r"(a) : "l"(p));
    return a;
}
__device__ __forceinline__ void cp16(uint32_t d, const void* s) {
    asm volatile("cp.async.cg.shared.global [%0], [%1], 16;" :: "r"(d), "l"(s));
}
__device__ __forceinline__ void cp16z(uint32_t d, const void* s, int sz) {
    asm volatile("cp.async.cg.shared.global [%0], [%1], 16, %2;" :: "r"(d), "l"(s), "r"(sz));
}
__device__ __forceinline__ void cpcommit() { asm volatile("cp.async.commit_group;"); }
template <int N>
__device__ __forceinline__ void cpwait() { asm volatile("cp.async.wait_group %0;" :: "n"(N)); }
__device__ __forceinline__ int ld_acq(const int* p) {
    int v; asm volatile("ld.acquire.gpu.global.b32 %0, [%1];" : "=r"(v) : "l"(p)); return v;
}
__device__ __forceinline__ void red_rel(int* p) {
    asm volatile("red.release.gpu.global.add.s32 [%0], 1;" :: "l"(p));
}
__device__ __forceinline__ void mma16(float* d, const uint32_t* a, const uint32_t* b) {
    asm volatile(
        "mma.sync.aligned.m16n8k16.row.col.f32.f16.f16.f32 "
        "{%0,%1,%2,%3},{%4,%5,%6,%7},{%8,%9},{%0,%1,%2,%3};"
        : "+f"(d[0]), "+f"(d[1]), "+f"(d[2]), "+f"(d[3])
        : "r"(a[0]), "r"(a[1]), "r"(a[2]), "r"(a[3]), "r"(b[0]), "r"(b[1]));
}

// ---------------- stage issue ----------------
template <int EDGE>
__device__ __forceinline__ void stage_issue(
    __half* sm, int slot, const __half* __restrict__ A, const __half* __restrict__ W,
    int m0, int n0, int kt, int Nb, int tid)
{
    __half* dA = sm + slot * SLOT;
    __half* dB = dA + A_ST;
    const __half* Ap = A + (size_t)m0 * 1024 + kt * 32;
    const __half* Wp = W + (size_t)n0 * 1024 + kt * 32;
#pragma unroll
    for (int i = 0; i < 2; i++) {
        int idx = tid + (i << 8);
        int row = idx >> 2, q = idx & 3;
        cp16(smaddr(dA + row * 32 + q * 8), Ap + (size_t)row * 1024 + q * 8);
    }
#pragma unroll
    for (int i = 0; i < 4; i++) {
        int idx = tid + (i << 8);
        int row = idx >> 2, q = idx & 3;
        if (EDGE) {
            int ok = (n0 + row < Nb);
            cp16z(smaddr(dB + row * 32 + q * 8),
                  Wp + (size_t)(ok ? row : 0) * 1024 + q * 8, ok ? 16 : 0);
        } else {
            cp16(smaddr(dB + row * 32 + q * 8), Wp + (size_t)row * 1024 + q * 8);
        }
    }
    cpcommit();
}

// ---------------- stage compute: 64x64 warp tile, 64 MMAs ----------------
__device__ __forceinline__ void stage_compute(
    const __half* sm, int slot, int wm, int wn, int g, int tig, float acc[4][8][4])
{
    const __half* bA = sm + slot * SLOT + (size_t)(wm * 64 + g) * 32 + tig * 8;
    const __half* bB = sm + slot * SLOT + A_ST + (size_t)(wn * 64 + g) * 32 + tig * 8;
    uint4 bq[8];
#pragma unroll
    for (int ni = 0; ni < 8; ni++)
        bq[ni] = *(const uint4*)(bB + ni * 8 * 32);
#pragma unroll
    for (int mi = 0; mi < 4; mi++) {
        uint4 alo = *(const uint4*)(bA + mi * 16 * 32);
        uint4 ahi = *(const uint4*)(bA + (mi * 16 + 8) * 32);
        uint32_t af0[4] = {alo.x, ahi.x, alo.y, ahi.y};
        uint32_t af1[4] = {alo.z, ahi.z, alo.w, ahi.w};
#pragma unroll
        for (int ni = 0; ni < 8; ni++) {
            uint32_t bf0[2] = {bq[ni].x, bq[ni].y};
            uint32_t bf1[2] = {bq[ni].z, bq[ni].w};
            mma16(acc[mi][ni], af0, bf0);
            mma16(acc[mi][ni], af1, bf1);
        }
    }
}

// ---------------- full K=1024 mainloop ----------------
template <int EDGE>
__device__ __forceinline__ void run_mainloop(
    __half* sm, const __half* __restrict__ A, const __half* __restrict__ W,
    int m0, int n0, int Nb, float acc[4][8][4],
    int tid, int wm, int wn, int g, int tig)
{
    stage_issue<EDGE>(sm, 0, A, W, m0, n0, 0, Nb, tid);
    stage_issue<EDGE>(sm, 1, A, W, m0, n0, 1, Nb, tid);
    stage_issue<EDGE>(sm, 2, A, W, m0, n0, 2, Nb, tid);
#pragma unroll 1
    for (int kt = 0; kt < 32; kt++) {
        int slot = kt & 3;
        if (kt < 30)       cpwait<2>();
        else if (kt == 30) cpwait<1>();
        else               cpwait<0>();
        __syncthreads();
        if (kt + 3 < 32) stage_issue<EDGE>(sm, (kt + 3) & 3, A, W, m0, n0, kt + 3, Nb, tid);
        stage_compute(sm, slot, wm, wn, g, tig, acc);
    }
}

// ---------------- LSTM tile epilogue (shared by DAG kernel) ----------------
__device__ __forceinline__ void lstm_epilogue(
    float acc[4][8][4], __half* hsm,
    const float* __restrict__ xg, const float* __restrict__ Cin,
    float* __restrict__ Cout, __half* __restrict__ Hout, __half* __restrict__ Hfin,
    int m0, int n0, int final_t, int tid, int wm, int wn, int g, int tig)
{
#pragma unroll
    for (int mi = 0; mi < 4; mi++) {
        const int R0 = m0 + wm * 64 + mi * 16;
#pragma unroll
        for (int ni = 0; ni < 8; ni++) {
            const int V0 = n0 + wn * 64 + ni * 8;
            float c0 = acc[mi][ni][0], c1 = acc[mi][ni][1];
            float c2 = acc[mi][ni][2], c3 = acc[mi][ni][3];
            int p = tig & 1;
            float x = p ? c0 : c2, y = p ? c1 : c3;
            float sx = __shfl_xor_sync(0xffffffffu, x, 1);
            float sy = __shfl_xor_sync(0xffffffffu, y, 1);
            float pi, pf, pg, po; int row;
            if (!p) { pi = c0; pf = c1; pg = sx; po = sy; row = R0 + g; }
            else    { pi = sx; pf = sy; pg = c2; po = c3; row = R0 + g + 8; }
            int u = (V0 >> 2) + (tig >> 1);
            float4 xv = *(const float4*)(xg + (size_t)row * G4 + u * 4);
            float ci = __ldcg(&Cin[(size_t)row * 1024 + u]);
            float cn = sigf(pf + xv.y) * ci + sigf(pi + xv.x) * tanhf(pg + xv.z);
            float hv = sigf(po + xv.w) * tanhf(cn);
            Cout[(size_t)row * 1024 + u] = cn;
            int ul = u - (n0 >> 2);
            hsm[(row - m0) * 64 + (ul & 32) + inv_l(ul & 31)] = __float2half_rn(hv);
        }
    }
    __syncthreads();
    {
        int r = tid >> 1, seg = tid & 1;
        int m = m0 + r;
        const uint4* src = (const uint4*)(hsm + r * 64 + seg * 32);
        uint4 a = src[0], b = src[1], c = src[2], d = src[3];
        __half* gd = Hout + (size_t)m * 1024 + (n0 >> 2) + seg * 32;
        ((uint4*)gd)[0] = a; ((uint4*)gd)[1] = b; ((uint4*)gd)[2] = c; ((uint4*)gd)[3] = d;
        if ((m >> 8) == final_t) {
            __half* fd = Hfin + (size_t)m * 1024 + (n0 >> 2) + seg * 32;
            ((uint4*)fd)[0] = a; ((uint4*)fd)[1] = b; ((uint4*)fd)[2] = c; ((uint4*)fd)[3] = d;
        }
    }
}

// ---------------- persistent DAG kernel: all 15 unroll steps ----------------
__global__ void __launch_bounds__(256, 1) k_dag_lstm(
    __half* __restrict__ hu0, __half* __restrict__ hu1,
    const __half* __restrict__ Whh, const float* __restrict__ xg,
    float* __restrict__ cu, __half* __restrict__ hn)
{
    extern __shared__ __half sm[];
    __half* hsm = sm + MAIN_H;
    __shared__ int s_wid;
    const int tid = threadIdx.x, lane = tid & 31, wid = tid >> 5;
    const int wm = wid & 1, wn = wid >> 1, g = lane >> 2, tig = lane & 3;

#pragma unroll 1
    while (true) {
        __syncthreads();
        if (tid == 0) s_wid = atomicAdd(&g_work, 1);
        __syncthreads();
        int w = s_wid;
        if (w >= TOT_TILES) break;

        int j = 0;
#pragma unroll 1
        for (; j < NSTEP; j++) {
            int na = (15 - j < 14) ? (15 - j) : 14;
            int sz = na << 5;
            if (w < sz) break;
            w -= sz;
        }
        int mb = w >> 4, nb = w & 15;
        int m0 = mb * 128, n0 = nb * 256;

        if (j > 0) {
            if (tid == 0) {
                const int* cp = &g_cnt[(j - 1) * 28 + mb];
                while (ld_acq(cp) < 16) {}
            }
            __syncthreads();
        }

        const __half* Hin = (j & 1) ? hu1 : hu0;
        __half*       Ho  = (j & 1) ? hu0 : hu1;

        float acc[4][8][4];
#pragma unroll
        for (int a = 0; a < 4; a++)
#pragma unroll
            for (int b = 0; b < 8; b++)
#pragma unroll
                for (int c = 0; c < 4; c++) acc[a][b][c] = 0.f;

        run_mainloop<0>(sm, Hin, Whh, m0, n0, 0x7fffffff, acc, tid, wm, wn, g, tig);
        lstm_epilogue(acc, hsm, xg, cu, cu, Ho, hn, m0, n0, 14 - j,
                      tid, wm, wn, g, tig);

        __threadfence();
        __syncthreads();
        if (tid == 0) red_rel(&g_cnt[j * 28 + mb]);
    }
}

// ---------------- merged projection GEMMs (gridDim.z selects set) ----------------
__global__ void __launch_bounds__(256, 1) k_mma_proj(
    const __half* __restrict__ A,
    const __half* __restrict__ W0, float* __restrict__ O0,
    const float* __restrict__ b00, const float* __restrict__ b01,
    const __half* __restrict__ W1, float* __restrict__ O1,
    const float* __restrict__ b10, const float* __restrict__ b11)
{
    extern __shared__ __half sm[];
    float* biasS = (float*)(sm + MAIN_H);
    const int tid = threadIdx.x, lane = tid & 31, wid = tid >> 5;
    const int wm = wid & 1, wn = wid >> 1, g = lane >> 2, tig = lane & 3;
    const int m0 = blockIdx.y * 128, n0 = blockIdx.x * 256;
    const int sel = blockIdx.z;
    const __half* W = sel ? W1 : W0;
    float* Out = sel ? O1 : O0;
    const float* b0 = sel ? b10 : b00;
    const float* b1 = sel ? b11 : b01;

    {
        int np = n0 + tid;
        int wr = ((np & 3) << 10) | (np >> 2);
        biasS[tid] = b0[wr] + b1[wr];
    }

    float acc[4][8][4];
#pragma unroll
    for (int a = 0; a < 4; a++)
#pragma unroll
        for (int b = 0; b < 8; b++)
#pragma unroll
            for (int c = 0; c < 4; c++) acc[a][b][c] = 0.f;

    run_mainloop<0>(sm, A, W, m0, n0, 0x7fffffff, acc, tid, wm, wn, g, tig);

#pragma unroll
    for (int mi = 0; mi < 4; mi++) {
        const int R0 = m0 + wm * 64 + mi * 16;
#pragma unroll
        for (int ni = 0; ni < 8; ni++) {
            const int v = n0 + wn * 64 + ni * 8 + 2 * tig;
            const float bA0 = biasS[v - n0], bA1 = biasS[v - n0 + 1];
            const int r1 = R0 + g, r2 = R0 + g + 8;
            float2 s1 = make_float2(acc[mi][ni][0] + bA0, acc[mi][ni][1] + bA1);
            float2 s2 = make_float2(acc[mi][ni][2] + bA0, acc[mi][ni][3] + bA1);
            *(float2*)(Out + (size_t)r1 * G4 + v) = s1;
            *(float2*)(Out + (size_t)r2 * G4 + v) = s2;
        }
    }
}

// ---------------- classifier ----------------
__global__ void __launch_bounds__(256, 1) k_mma_cls(
    const __half* __restrict__ A, const __half* __restrict__ W,
    float* __restrict__ Out, const float* __restrict__ b0, int N)
{
    extern __shared__ __half sm[];
    float* biasS = (float*)(sm + MAIN_H);
    const int tid = threadIdx.x, lane = tid & 31, wid = tid >> 5;
    const int wm = wid & 1, wn = wid >> 1, g = lane >> 2, tig = lane & 3;
    const int m0 = blockIdx.y * 128, n0 = blockIdx.x * 256;

    {
        int np = n0 + tid;
        biasS[tid] = (np < N) ? b0[np] : 0.f;
    }

    float acc[4][8][4];
#pragma unroll
    for (int a = 0; a < 4; a++)
#pragma unroll
        for (int b = 0; b < 8; b++)
#pragma unroll
            for (int c = 0; c < 4; c++) acc[a][b][c] = 0.f;

    run_mainloop<1>(sm, A, W, m0, n0, N, acc, tid, wm, wn, g, tig);

#pragma unroll
    for (int mi = 0; mi < 4; mi++) {
        const int R0 = m0 + wm * 64 + mi * 16;
#pragma unroll
        for (int ni = 0; ni < 8; ni++) {
            const int v = n0 + wn * 64 + ni * 8 + 2 * tig;
            const float bA0 = biasS[v - n0], bA1 = biasS[v - n0 + 1];
            const int r1 = R0 + g, r2 = R0 + g + 8;
            int or1 = (r1 & 255) * S_ + (r1 >> 8);
            int or2 = (r2 & 255) * S_ + (r2 >> 8);
            if (v < N) {
                Out[(size_t)or1 * N + v] = acc[mi][ni][0] + bA0;
                Out[(size_t)or2 * N + v] = acc[mi][ni][2] + bA0;
            }
            if (v + 1 < N) {
                Out[(size_t)or1 * N + v + 1] = acc[mi][ni][1] + bA1;
                Out[(size_t)or2 * N + v + 1] = acc[mi][ni][3] + bA1;
            }
        }
    }
}

// ---------------- prep kernels (fp32 -> fp16 + k-permute) ----------------
template <int REMAP>
__global__ void k_prep_w(const float* __restrict__ in, __half* __restrict__ out, int rows) {
    int idx = blockIdx.x * blockDim.x + threadIdx.x;
    if (idx >= rows * 32) return;
    int r = idx >> 5, b32 = idx & 31;
    int wr = REMAP ? (((r & 3) << 10) | (r >> 2)) : r;
    const float* src = in + (size_t)wr * 1024 + b32 * 32;
    float v[32];
#pragma unroll
    for (int i = 0; i < 8; i++) *(float4*)&v[i * 4] = *(const float4*)(src + i * 4);
    __half h[32];
#pragma unroll
    for (int p = 0; p < 32; p++) h[p] = __float2half_rn(v[perm_l(p)]);
    uint4* dst = (uint4*)(out + (size_t)r * 1024 + b32 * 32);
#pragma unroll
    for (int i = 0; i < 4; i++) dst[i] = ((const uint4*)h)[i];
}

__global__ void k_xTh(const float* __restrict__ in, __half* __restrict__ out) {
    int idx = blockIdx.x * blockDim.x + threadIdx.x;
    if (idx >= SB * 32) return;
    int r = idx >> 5, b32 = idx & 31;
    int b = r % B_, s = r / B_;
    const float* src = in + (size_t)(b * S_ + s) * 1024 + b32 * 32;
    float v[32];
#pragma unroll
    for (int i = 0; i < 8; i++) *(float4*)&v[i * 4] = *(const float4*)(src + i * 4);
    __half h[32];
#pragma unroll
    for (int p = 0; p < 32; p++) h[p] = __float2half_rn(v[perm_l(p)]);
    uint4* dst = (uint4*)(out + (size_t)r * 1024 + b32 * 32);
#pragma unroll
    for (int i = 0; i < 4; i++) dst[i] = ((const uint4*)h)[i];
}

__global__ void k_h2h(const float* __restrict__ in, __half* __restrict__ out) {
    int idx = blockIdx.x * blockDim.x + threadIdx.x;
    if (idx >= SB * 32) return;
    int r = idx >> 5, b32 = idx & 31;
    const float* src = in + (size_t)r * 1024 + b32 * 32;
    float v[32];
#pragma unroll
    for (int i = 0; i < 8; i++) *(float4*)&v[i * 4] = *(const float4*)(src + i * 4);
    __half h[32];
#pragma unroll
    for (int p = 0; p < 32; p++) h[p] = __float2half_rn(v[perm_l(p)]);
    uint4* dst = (uint4*)(out + (size_t)r * 1024 + b32 * 32);
#pragma unroll
    for (int i = 0; i < 4; i++) dst[i] = ((const uint4*)h)[i];
}

// ---------------- FFMA rolling LSTM step (fp32-exact, M=256) ----------------
__global__ void __launch_bounds__(256) k_lstm_step(
    const float* __restrict__ Hin, const float* __restrict__ Whh,
    const float* __restrict__ xg, const float* __restrict__ Cin,
    float* __restrict__ Hout, float* __restrict__ Cout, int zeroInit)
{
    constexpr int BM = 64, TM = 4;
    __shared__ float As[16][BM + 4];
    __shared__ float Ws[16][132];
    const int tid = threadIdx.x;
    const int tx = tid & 15, ty = tid >> 4;
    const int m0 = blockIdx.y * BM;
    const int n0 = blockIdx.x * 128;

    float acc[TM][8];
#pragma unroll
    for (int i = 0; i < TM; i++)
#pragma unroll
        for (int j = 0; j < 8; j++) acc[i][j] = 0.f;

    if (!zeroInit) {
        const int lr = tid >> 2;
        const int lk = (tid & 3) << 2;
        for (int kt = 0; kt < 1024; kt += 16) {
            {
                int row = lr;
                float4 v = *(const float4*)&Hin[(size_t)(m0 + row) * 1024 + kt + lk];
                As[lk + 0][row] = v.x; As[lk + 1][row] = v.y;
                As[lk + 2][row] = v.z; As[lk + 3][row] = v.w;
            }
#pragma unroll
            for (int r = 0; r < 2; r++) {
                int wr2 = lr + r * 64;
                int np = n0 + wr2;
                int wrow = ((np & 3) << 10) + (np >> 2);
                float4 v = *(const float4*)&Whh[(size_t)wrow * 1024 + kt + lk];
                Ws[lk + 0][wr2] = v.x; Ws[lk + 1][wr2] = v.y;
                Ws[lk + 2][wr2] = v.z; Ws[lk + 3][wr2] = v.w;
            }
            __syncthreads();
#pragma unroll
            for (int k = 0; k < 16; k++) {
                float a[TM], wv[8];
#pragma unroll
                for (int i = 0; i < TM; i++) a[i] = As[k][ty * TM + i];
#pragma unroll
                for (int j = 0; j < 8; j++) wv[j] = Ws[k][tx * 8 + j];
#pragma unroll
                for (int i = 0; i < TM; i++)
#pragma unroll
                    for (int j = 0; j < 8; j++) acc[i][j] = fmaf(a[i], wv[j], acc[i][j]);
            }
            __syncthreads();
        }
    }

    const int u0 = (n0 + tx * 8) >> 2;
#pragma unroll
    for (int i = 0; i < TM; i++) {
        int m = m0 + ty * TM + i;
        const float* xr = xg + (size_t)m * G4;
#pragma unroll
        for (int uu = 0; uu < 2; uu++) {
            int u = u0 + uu;
            float4 xv = *(const float4*)&xr[(size_t)u * 4];
            float pi = acc[i][uu * 4 + 0] + xv.x;
            float pf = acc[i][uu * 4 + 1] + xv.y;
            float pg = acc[i][uu * 4 + 2] + xv.z;
            float po = acc[i][uu * 4 + 3] + xv.w;
            float c  = zeroInit ? 0.f : Cin[(size_t)m * 1024 + u];
            float c2 = sigf(pf) * c + sigf(pi) * tanhf(pg);
            float h2 = sigf(po) * tanhf(c2);
            Hout[(size_t)m * 1024 + u] = h2;
            Cout[(size_t)m * 1024 + u] = c2;
        }
    }
}

// ---------------- host orchestration ----------------
extern "C" void kernel_launch(void* const* d_in, const int* in_sizes, int n_in,
                              void* d_out, int out_size) {
    (void)in_sizes; (void)n_in; (void)out_size;
    const float* inp   = (const float*)d_in[0];
    const float* Wih_r = (const float*)d_in[1];
    const float* Whh_r = (const float*)d_in[2];
    const float* bih_r = (const float*)d_in[3];
    const float* bhh_r = (const float*)d_in[4];
    const float* Wih_u = (const float*)d_in[5];
    const float* Whh_u = (const float*)d_in[6];
    const float* bih_u = (const float*)d_in[7];
    const float* bhh_u = (const float*)d_in[8];
    const float* Wc    = (const float*)d_in[9];
    const float* bc    = (const float*)d_in[10];
    float* out = (float*)d_out;

    __half *xT, *hu, *hn, *wihr, *wihu, *whhu, *wc;
    float *xg_r, *xg_u, *hs, *cs, *cu;
    int *workp, *cntp;
    cudaGetSymbolAddress((void**)&xT,   g_xT);
    cudaGetSymbolAddress((void**)&xg_r, g_xg_r);
    cudaGetSymbolAddress((void**)&xg_u, g_xg_u);
    cudaGetSymbolAddress((void**)&hs,   g_hs);
    cudaGetSymbolAddress((void**)&cs,   g_cs);
    cudaGetSymbolAddress((void**)&hu,   g_hu);
    cudaGetSymbolAddress((void**)&cu,   g_cu);
    cudaGetSymbolAddress((void**)&hn,   g_hn);
    cudaGetSymbolAddress((void**)&wihr, g_wihr);
    cudaGetSymbolAddress((void**)&wihu, g_wihu);
    cudaGetSymbolAddress((void**)&whhu, g_whhu);
    cudaGetSymbolAddress((void**)&wc,   g_wc);
    cudaGetSymbolAddress((void**)&workp, g_work);
    cudaGetSymbolAddress((void**)&cntp,  g_cnt);
    __half* hu0 = hu;
    __half* hu1 = hu + (size_t)SB * 1024;

    cudaFuncSetAttribute(k_dag_lstm, cudaFuncAttributeMaxDynamicSharedMemorySize, SMEM_LSTM);
    cudaFuncSetAttribute(k_mma_proj, cudaFuncAttributeMaxDynamicSharedMemorySize, SMEM_LIN);
    cudaFuncSetAttribute(k_mma_cls,  cudaFuncAttributeMaxDynamicSharedMemorySize, SMEM_LIN);

    // 0) prep (launches 1-5)
    k_xTh<<<(SB * 32 + 255) / 256, 256>>>(inp, xT);
    k_prep_w<1><<<(G4 * 32 + 255) / 256, 256>>>(Wih_r, wihr, G4);
    k_prep_w<1><<<(G4 * 32 + 255) / 256, 256>>>(Wih_u, wihu, G4);
    k_prep_w<1><<<(G4 * 32 + 255) / 256, 256>>>(Whh_u, whhu, G4);
    k_prep_w<0><<<(C_ * 32 + 255) / 256, 256>>>(Wc, wc, C_);

    // 1) merged input projections (launch 6 — ncu target)
    {
        dim3 g(16, 28, 2);
        k_mma_proj<<<g, 256, SMEM_LIN>>>(xT,
                                         wihr, xg_r, bih_r, bhh_r,
                                         wihu, xg_u, bih_u, bhh_u);
    }

    // 2) rolling LSTM: 14 sequential FFMA steps (fp32-exact)
    for (int t = 0; t < S_; t++) {
        dim3 g(G4 / 128, B_ / 64);
        const float* hin = (t == 0) ? nullptr : hs + (size_t)(t - 1) * BH;
        const float* cin = (t == 0) ? nullptr : cs + (size_t)(t - 1) * BH;
        k_lstm_step<<<g, 256>>>(hin, Whh_r,
                                xg_r + (size_t)t * B_ * G4, cin,
                                hs + (size_t)t * BH, cs + (size_t)t * BH,
                                (t == 0) ? 1 : 0);
    }

    // 3) init unroll state + DAG bookkeeping
    k_h2h<<<(SB * 32 + 255) / 256, 256>>>(hs, hu0);
    cudaMemcpyAsync(cu, cs, sizeof(float) * (size_t)SB * 1024, cudaMemcpyDeviceToDevice, 0);
    cudaMemsetAsync(workp, 0, sizeof(int), 0);
    cudaMemsetAsync(cntp, 0, sizeof(int) * NSTEP * 28, 0);

    // 4) all 15 unroll steps in ONE persistent DAG kernel
    k_dag_lstm<<<NSM, 256, SMEM_LSTM>>>(hu0, hu1, whhu, xg_u, cu, hn);

    // 5) classifier
    {
        dim3 g(10, 28);
        k_mma_cls<<<g, 256, SMEM_LIN>>>(hn, wc, out, bc, C_);
    }
}

// round 7
// speedup vs baseline: 1.1210x; 1.1210x over previous
#include <cuda_runtime.h>
#include <cuda_fp16.h>
#include <math.h>
#include <stdint.h>

// ---------------- problem constants ----------------
#define B_ 256
#define S_ 14
#define C_ 2513
#define SB 3584          // S_*B_
#define BH 262144        // B_*H_
#define G4 4096          // 4*H_

// ---------------- fp16 mma GEMM config ----------------
// CTA tile 256x128, 512 threads, 16 warps (4m x 4n), warp tile 64x32,
// K-chunk 32, 4-stage cp.async.
#define A_ST 8192                 // 256*32 halves
#define B_ST 4096                 // 128*32 halves
#define SLOT (A_ST + B_ST)        // 12288 halves = 24KB
#define NST  4
#define MAIN_H (NST * SLOT)       // 49152 halves = 96KB
#define SMEM_LSTM ((MAIN_H + 256 * 32) * 2)   // + h tile 16KB = 114688 B
#define SMEM_LIN  (MAIN_H * 2 + 512)          // + bias 128 floats = 98816 B

// ---------------- scratch (device globals) ----------------
__device__ __half g_xT [SB * 1024];
__device__ float  g_xg_r[(size_t)SB * G4];
__device__ float  g_xg_u[(size_t)SB * G4];
__device__ float  g_hs [SB * 1024];
__device__ float  g_cs [SB * 1024];
__device__ __half g_hu [2 * SB * 1024];
__device__ float  g_cu [SB * 1024];
__device__ __half g_hn [SB * 1024];
__device__ __half g_wihr[(size_t)G4 * 1024];
__device__ __half g_wihu[(size_t)G4 * 1024];
__device__ __half g_whhu[(size_t)G4 * 1024];
__device__ __half g_wc [(size_t)2560 * 1024];

__device__ __forceinline__ float sigf(float x) { return 1.0f / (1.0f + expf(-x)); }

// logical-k permutation within each 32-k block
__device__ __forceinline__ int perm_l(int p) {
    int b = (p >> 2) & 1, t = p >> 3, j = p & 3;
    return b * 16 + ((j < 2) ? (2 * t + j) : (2 * t + 8 + (j - 2)));
}
__device__ __forceinline__ int inv_l(int l) {
    int b = l >> 4, r = l & 15, hi = r >> 3, t = (r >> 1) & 3, e = r & 1;
    return t * 8 + b * 4 + hi * 2 + e;
}

// ---------------- low-level helpers ----------------
__device__ __forceinline__ uint32_t smaddr(const void* p) {
    uint32_t a;
    asm("{ .reg .u64 t; cvta.to.shared.u64 t, %1; cvt.u32.u64 %0, t; }" : "=r"(a) : "l"(p));
    return a;
}
__device__ __forceinline__ void cp16(uint32_t d, const void* s) {
    asm volatile("cp.async.cg.shared.global [%0], [%1], 16;" :: "r"(d), "l"(s));
}
__device__ __forceinline__ void cp16z(uint32_t d, const void* s, int sz) {
    asm volatile("cp.async.cg.shared.global [%0], [%1], 16, %2;" :: "r"(d), "l"(s), "r"(sz));
}
__device__ __forceinline__ void cpcommit() { asm volatile("cp.async.commit_group;"); }
template <int N>
__device__ __forceinline__ void cpwait() { asm volatile("cp.async.wait_group %0;" :: "n"(N)); }
__device__ __forceinline__ void mma16(float* d, const uint32_t* a, const uint32_t* b) {
    asm volatile(
        "mma.sync.aligned.m16n8k16.row.col.f32.f16.f16.f32 "
        "{%0,%1,%2,%3},{%4,%5,%6,%7},{%8,%9},{%0,%1,%2,%3};"
        : "+f"(d[0]), "+f"(d[1]), "+f"(d[2]), "+f"(d[3])
        : "r"(a[0]), "r"(a[1]), "r"(a[2]), "r"(a[3]), "r"(b[0]), "r"(b[1]));
}

// ---------------- stage issue (512 threads) ----------------
template <int EDGE>
__device__ __forceinline__ void stage_issue(
    __half* sm, int slot, const __half* __restrict__ A, const __half* __restrict__ W,
    int m0, int n0, int kt, int Nb, int tid)
{
    __half* dA = sm + slot * SLOT;
    __half* dB = dA + A_ST;
    const __half* Ap = A + (size_t)m0 * 1024 + kt * 32;
    const __half* Wp = W + (size_t)n0 * 1024 + kt * 32;
#pragma unroll
    for (int i = 0; i < 2; i++) {                 // A: 256 rows
        int idx = tid + (i << 9);
        int row = idx >> 2, q = idx & 3;
        cp16(smaddr(dA + row * 32 + q * 8), Ap + (size_t)row * 1024 + q * 8);
    }
    {                                             // B: 128 rows
        int row = tid >> 2, q = tid & 3;
        if (EDGE) {
            int ok = (n0 + row < Nb);
            cp16z(smaddr(dB + row * 32 + q * 8),
                  Wp + (size_t)(ok ? row : 0) * 1024 + q * 8, ok ? 16 : 0);
        } else {
            cp16(smaddr(dB + row * 32 + q * 8), Wp + (size_t)row * 1024 + q * 8);
        }
    }
    cpcommit();
}

// ---------------- stage compute: 64x32 warp tile, 32 MMAs ----------------
__device__ __forceinline__ void stage_compute(
    const __half* sm, int slot, int wm, int wn, int g, int tig, float acc[4][4][4])
{
    const __half* bA = sm + slot * SLOT + (size_t)(wm * 64 + g) * 32 + tig * 8;
    const __half* bB = sm + slot * SLOT + A_ST + (size_t)(wn * 32 + g) * 32 + tig * 8;
    uint4 bq[4];
#pragma unroll
    for (int ni = 0; ni < 4; ni++)
        bq[ni] = *(const uint4*)(bB + ni * 8 * 32);
#pragma unroll
    for (int mi = 0; mi < 4; mi++) {
        uint4 alo = *(const uint4*)(bA + mi * 16 * 32);
        uint4 ahi = *(const uint4*)(bA + (mi * 16 + 8) * 32);
        uint32_t af0[4] = {alo.x, ahi.x, alo.y, ahi.y};
        uint32_t af1[4] = {alo.z, ahi.z, alo.w, ahi.w};
#pragma unroll
        for (int ni = 0; ni < 4; ni++) {
            uint32_t bf0[2] = {bq[ni].x, bq[ni].y};
            uint32_t bf1[2] = {bq[ni].z, bq[ni].w};
            mma16(acc[mi][ni], af0, bf0);
            mma16(acc[mi][ni], af1, bf1);
        }
    }
}

// ---------------- full K=1024 mainloop ----------------
template <int EDGE>
__device__ __forceinline__ void run_mainloop(
    __half* sm, const __half* __restrict__ A, const __half* __restrict__ W,
    int m0, int n0, int Nb, float acc[4][4][4],
    int tid, int wm, int wn, int g, int tig)
{
    stage_issue<EDGE>(sm, 0, A, W, m0, n0, 0, Nb, tid);
    stage_issue<EDGE>(sm, 1, A, W, m0, n0, 1, Nb, tid);
    stage_issue<EDGE>(sm, 2, A, W, m0, n0, 2, Nb, tid);
#pragma unroll 1
    for (int kt = 0; kt < 32; kt++) {
        int slot = kt & 3;
        if (kt < 30)       cpwait<2>();
        else if (kt == 30) cpwait<1>();
        else               cpwait<0>();
        __syncthreads();
        if (kt + 3 < 32) stage_issue<EDGE>(sm, (kt + 3) & 3, A, W, m0, n0, kt + 3, Nb, tid);
        stage_compute(sm, slot, wm, wn, g, tig, acc);
    }
}

// ---------------- fused tensor-core LSTM step (per unroll step) ----------------
__global__ void __launch_bounds__(512, 1) k_mma_lstm(
    const __half* __restrict__ Hin, const __half* __restrict__ Whh,
    const float* __restrict__ xg, const float* __restrict__ Cin,
    __half* __restrict__ Hout, float* __restrict__ Cout,
    __half* __restrict__ Hfin, int final_t)
{
    extern __shared__ __half sm[];
    __half* hsm = sm + MAIN_H;
    const int tid = threadIdx.x, lane = tid & 31, wid = tid >> 5;
    const int wm = wid & 3, wn = wid >> 2, g = lane >> 2, tig = lane & 3;
    const int m0 = blockIdx.y * 256, n0 = blockIdx.x * 128;

    float acc[4][4][4];
#pragma unroll
    for (int a = 0; a < 4; a++)
#pragma unroll
        for (int b = 0; b < 4; b++)
#pragma unroll
            for (int c = 0; c < 4; c++) acc[a][b][c] = 0.f;

    run_mainloop<0>(sm, Hin, Whh, m0, n0, 0x7fffffff, acc, tid, wm, wn, g, tig);

#pragma unroll
    for (int mi = 0; mi < 4; mi++) {
        const int R0 = m0 + wm * 64 + mi * 16;
#pragma unroll
        for (int ni = 0; ni < 4; ni++) {
            const int V0 = n0 + wn * 32 + ni * 8;
            float c0 = acc[mi][ni][0], c1 = acc[mi][ni][1];
            float c2 = acc[mi][ni][2], c3 = acc[mi][ni][3];
            int p = tig & 1;
            float x = p ? c0 : c2, y = p ? c1 : c3;
            float sx = __shfl_xor_sync(0xffffffffu, x, 1);
            float sy = __shfl_xor_sync(0xffffffffu, y, 1);
            float pi, pf, pg, po; int row;
            if (!p) { pi = c0; pf = c1; pg = sx; po = sy; row = R0 + g; }
            else    { pi = sx; pf = sy; pg = c2; po = c3; row = R0 + g + 8; }
            int u = (V0 >> 2) + (tig >> 1);
            float4 xv = *(const float4*)(xg + (size_t)row * G4 + u * 4);
            float ci = Cin[(size_t)row * 1024 + u];
            float cn = sigf(pf + xv.y) * ci + sigf(pi + xv.x) * tanhf(pg + xv.z);
            float hv = sigf(po + xv.w) * tanhf(cn);
            Cout[(size_t)row * 1024 + u] = cn;
            int ul = u - (n0 >> 2);
            hsm[(row - m0) * 32 + inv_l(ul)] = __float2half_rn(hv);
        }
    }
    __syncthreads();
    // coalesced permuted-h store: 256 rows x 64B
    {
        int r = tid >> 1, seg = tid & 1;
        int m = m0 + r;
        const uint4* src = (const uint4*)(hsm + r * 32 + seg * 16);
        uint4 a = src[0], b = src[1];
        __half* gd = Hout + (size_t)m * 1024 + (n0 >> 2) + seg * 16;
        ((uint4*)gd)[0] = a; ((uint4*)gd)[1] = b;
        if ((m >> 8) == final_t) {
            __half* fd = Hfin + (size_t)m * 1024 + (n0 >> 2) + seg * 16;
            ((uint4*)fd)[0] = a; ((uint4*)fd)[1] = b;
        }
    }
}

// ---------------- merged projection GEMMs ----------------
__global__ void __launch_bounds__(512, 1) k_mma_proj(
    const __half* __restrict__ A,
    const __half* __restrict__ W0, float* __restrict__ O0,
    const float* __restrict__ b00, const float* __restrict__ b01,
    const __half* __restrict__ W1, float* __restrict__ O1,
    const float* __restrict__ b10, const float* __restrict__ b11)
{
    extern __shared__ __half sm[];
    float* biasS = (float*)(sm + MAIN_H);
    const int tid = threadIdx.x, lane = tid & 31, wid = tid >> 5;
    const int wm = wid & 3, wn = wid >> 2, g = lane >> 2, tig = lane & 3;
    const int m0 = blockIdx.y * 256, n0 = blockIdx.x * 128;
    const int sel = blockIdx.z;
    const __half* W = sel ? W1 : W0;
    float* Out = sel ? O1 : O0;
    const float* b0 = sel ? b10 : b00;
    const float* b1 = sel ? b11 : b01;

    if (tid < 128) {
        int np = n0 + tid;
        int wr = ((np & 3) << 10) | (np >> 2);
        biasS[tid] = b0[wr] + b1[wr];
    }

    float acc[4][4][4];
#pragma unroll
    for (int a = 0; a < 4; a++)
#pragma unroll
        for (int b = 0; b < 4; b++)
#pragma unroll
            for (int c = 0; c < 4; c++) acc[a][b][c] = 0.f;

    run_mainloop<0>(sm, A, W, m0, n0, 0x7fffffff, acc, tid, wm, wn, g, tig);

#pragma unroll
    for (int mi = 0; mi < 4; mi++) {
        const int R0 = m0 + wm * 64 + mi * 16;
#pragma unroll
        for (int ni = 0; ni < 4; ni++) {
            const int v = n0 + wn * 32 + ni * 8 + 2 * tig;
            const float bA0 = biasS[v - n0], bA1 = biasS[v - n0 + 1];
            const int r1 = R0 + g, r2 = R0 + g + 8;
            float2 s1 = make_float2(acc[mi][ni][0] + bA0, acc[mi][ni][1] + bA1);
            float2 s2 = make_float2(acc[mi][ni][2] + bA0, acc[mi][ni][3] + bA1);
            *(float2*)(Out + (size_t)r1 * G4 + v) = s1;
            *(float2*)(Out + (size_t)r2 * G4 + v) = s2;
        }
    }
}

// ---------------- classifier ----------------
__global__ void __launch_bounds__(512, 1) k_mma_cls(
    const __half* __restrict__ A, const __half* __restrict__ W,
    float* __restrict__ Out, const float* __restrict__ b0, int N)
{
    extern __shared__ __half sm[];
    float* biasS = (float*)(sm + MAIN_H);
    const int tid = threadIdx.x, lane = tid & 31, wid = tid >> 5;
    const int wm = wid & 3, wn = wid >> 2, g = lane >> 2, tig = lane & 3;
    const int m0 = blockIdx.y * 256, n0 = blockIdx.x * 128;

    if (tid < 128) {
        int np = n0 + tid;
        biasS[tid] = (np < N) ? b0[np] : 0.f;
    }

    float acc[4][4][4];
#pragma unroll
    for (int a = 0; a < 4; a++)
#pragma unroll
        for (int b = 0; b < 4; b++)
#pragma unroll
            for (int c = 0; c < 4; c++) acc[a][b][c] = 0.f;

    run_mainloop<1>(sm, A, W, m0, n0, N, acc, tid, wm, wn, g, tig);

#pragma unroll
    for (int mi = 0; mi < 4; mi++) {
        const int R0 = m0 + wm * 64 + mi * 16;
#pragma unroll
        for (int ni = 0; ni < 4; ni++) {
            const int v = n0 + wn * 32 + ni * 8 + 2 * tig;
            const float bA0 = biasS[v - n0], bA1 = biasS[v - n0 + 1];
            const int r1 = R0 + g, r2 = R0 + g + 8;
            int or1 = (r1 & 255) * S_ + (r1 >> 8);
            int or2 = (r2 & 255) * S_ + (r2 >> 8);
            if (v < N) {
                Out[(size_t)or1 * N + v] = acc[mi][ni][0] + bA0;
                Out[(size_t)or2 * N + v] = acc[mi][ni][2] + bA0;
            }
            if (v + 1 < N) {
                Out[(size_t)or1 * N + v + 1] = acc[mi][ni][1] + bA1;
                Out[(size_t)or2 * N + v + 1] = acc[mi][ni][3] + bA1;
            }
        }
    }
}

// ---------------- prep kernels (fp32 -> fp16 + k-permute) ----------------
template <int REMAP>
__global__ void k_prep_w(const float* __restrict__ in, __half* __restrict__ out, int rows) {
    int idx = blockIdx.x * blockDim.x + threadIdx.x;
    if (idx >= rows * 32) return;
    int r = idx >> 5, b32 = idx & 31;
    int wr = REMAP ? (((r & 3) << 10) | (r >> 2)) : r;
    const float* src = in + (size_t)wr * 1024 + b32 * 32;
    float v[32];
#pragma unroll
    for (int i = 0; i < 8; i++) *(float4*)&v[i * 4] = *(const float4*)(src + i * 4);
    __half h[32];
#pragma unroll
    for (int p = 0; p < 32; p++) h[p] = __float2half_rn(v[perm_l(p)]);
    uint4* dst = (uint4*)(out + (size_t)r * 1024 + b32 * 32);
#pragma unroll
    for (int i = 0; i < 4; i++) dst[i] = ((const uint4*)h)[i];
}

__global__ void k_xTh(const float* __restrict__ in, __half* __restrict__ out) {
    int idx = blockIdx.x * blockDim.x + threadIdx.x;
    if (idx >= SB * 32) return;
    int r = idx >> 5, b32 = idx & 31;
    int b = r % B_, s = r / B_;
    const float* src = in + (size_t)(b * S_ + s) * 1024 + b32 * 32;
    float v[32];
#pragma unroll
    for (int i = 0; i < 8; i++) *(float4*)&v[i * 4] = *(const float4*)(src + i * 4);
    __half h[32];
#pragma unroll
    for (int p = 0; p < 32; p++) h[p] = __float2half_rn(v[perm_l(p)]);
    uint4* dst = (uint4*)(out + (size_t)r * 1024 + b32 * 32);
#pragma unroll
    for (int i = 0; i < 4; i++) dst[i] = ((const uint4*)h)[i];
}

__global__ void k_h2h(const float* __restrict__ in, __half* __restrict__ out) {
    int idx = blockIdx.x * blockDim.x + threadIdx.x;
    if (idx >= SB * 32) return;
    int r = idx >> 5, b32 = idx & 31;
    const float* src = in + (size_t)r * 1024 + b32 * 32;
    float v[32];
#pragma unroll
    for (int i = 0; i < 8; i++) *(float4*)&v[i * 4] = *(const float4*)(src + i * 4);
    __half h[32];
#pragma unroll
    for (int p = 0; p < 32; p++) h[p] = __float2half_rn(v[perm_l(p)]);
    uint4* dst = (uint4*)(out + (size_t)r * 1024 + b32 * 32);
#pragma unroll
    for (int i = 0; i < 4; i++) dst[i] = ((const uint4*)h)[i];
}

// ---------------- FFMA rolling LSTM step (fp32-exact, M=256) ----------------
__global__ void __launch_bounds__(256) k_lstm_step(
    const float* __restrict__ Hin, const float* __restrict__ Whh,
    const float* __restrict__ xg, const float* __restrict__ Cin,
    float* __restrict__ Hout, float* __restrict__ Cout, int zeroInit)
{
    constexpr int BM = 64, TM = 4;
    __shared__ float As[16][BM + 4];
    __shared__ float Ws[16][132];
    const int tid = threadIdx.x;
    const int tx = tid & 15, ty = tid >> 4;
    const int m0 = blockIdx.y * BM;
    const int n0 = blockIdx.x * 128;

    float acc[TM][8];
#pragma unroll
    for (int i = 0; i < TM; i++)
#pragma unroll
        for (int j = 0; j < 8; j++) acc[i][j] = 0.f;

    if (!zeroInit) {
        const int lr = tid >> 2;
        const int lk = (tid & 3) << 2;
        for (int kt = 0; kt < 1024; kt += 16) {
            {
                int row = lr;
                float4 v = *(const float4*)&Hin[(size_t)(m0 + row) * 1024 + kt + lk];
                As[lk + 0][row] = v.x; As[lk + 1][row] = v.y;
                As[lk + 2][row] = v.z; As[lk + 3][row] = v.w;
            }
#pragma unroll
            for (int r = 0; r < 2; r++) {
                int wr2 = lr + r * 64;
                int np = n0 + wr2;
                int wrow = ((np & 3) << 10) + (np >> 2);
                float4 v = *(const float4*)&Whh[(size_t)wrow * 1024 + kt + lk];
                Ws[lk + 0][wr2] = v.x; Ws[lk + 1][wr2] = v.y;
                Ws[lk + 2][wr2] = v.z; Ws[lk + 3][wr2] = v.w;
            }
            __syncthreads();
#pragma unroll
            for (int k = 0; k < 16; k++) {
                float a[TM], wv[8];
#pragma unroll
                for (int i = 0; i < TM; i++) a[i] = As[k][ty * TM + i];
#pragma unroll
                for (int j = 0; j < 8; j++) wv[j] = Ws[k][tx * 8 + j];
#pragma unroll
                for (int i = 0; i < TM; i++)
#pragma unroll
                    for (int j = 0; j < 8; j++) acc[i][j] = fmaf(a[i], wv[j], acc[i][j]);
            }
            __syncthreads();
        }
    }

    const int u0 = (n0 + tx * 8) >> 2;
#pragma unroll
    for (int i = 0; i < TM; i++) {
        int m = m0 + ty * TM + i;
        const float* xr = xg + (size_t)m * G4;
#pragma unroll
        for (int uu = 0; uu < 2; uu++) {
            int u = u0 + uu;
            float4 xv = *(const float4*)&xr[(size_t)u * 4];
            float pi = acc[i][uu * 4 + 0] + xv.x;
            float pf = acc[i][uu * 4 + 1] + xv.y;
            float pg = acc[i][uu * 4 + 2] + xv.z;
            float po = acc[i][uu * 4 + 3] + xv.w;
            float c  = zeroInit ? 0.f : Cin[(size_t)m * 1024 + u];
            float c2 = sigf(pf) * c + sigf(pi) * tanhf(pg);
            float h2 = sigf(po) * tanhf(c2);
            Hout[(size_t)m * 1024 + u] = h2;
            Cout[(size_t)m * 1024 + u] = c2;
        }
    }
}

// ---------------- host orchestration ----------------
extern "C" void kernel_launch(void* const* d_in, const int* in_sizes, int n_in,
                              void* d_out, int out_size) {
    (void)in_sizes; (void)n_in; (void)out_size;
    const float* inp   = (const float*)d_in[0];
    const float* Wih_r = (const float*)d_in[1];
    const float* Whh_r = (const float*)d_in[2];
    const float* bih_r = (const float*)d_in[3];
    const float* bhh_r = (const float*)d_in[4];
    const float* Wih_u = (const float*)d_in[5];
    const float* Whh_u = (const float*)d_in[6];
    const float* bih_u = (const float*)d_in[7];
    const float* bhh_u = (const float*)d_in[8];
    const float* Wc    = (const float*)d_in[9];
    const float* bc    = (const float*)d_in[10];
    float* out = (float*)d_out;

    __half *xT, *hu, *hn, *wihr, *wihu, *whhu, *wc;
    float *xg_r, *xg_u, *hs, *cs, *cu;
    cudaGetSymbolAddress((void**)&xT,   g_xT);
    cudaGetSymbolAddress((void**)&xg_r, g_xg_r);
    cudaGetSymbolAddress((void**)&xg_u, g_xg_u);
    cudaGetSymbolAddress((void**)&hs,   g_hs);
    cudaGetSymbolAddress((void**)&cs,   g_cs);
    cudaGetSymbolAddress((void**)&hu,   g_hu);
    cudaGetSymbolAddress((void**)&cu,   g_cu);
    cudaGetSymbolAddress((void**)&hn,   g_hn);
    cudaGetSymbolAddress((void**)&wihr, g_wihr);
    cudaGetSymbolAddress((void**)&wihu, g_wihu);
    cudaGetSymbolAddress((void**)&whhu, g_whhu);
    cudaGetSymbolAddress((void**)&wc,   g_wc);
    __half* hu0 = hu;
    __half* hu1 = hu + (size_t)SB * 1024;

    cudaFuncSetAttribute(k_mma_lstm, cudaFuncAttributeMaxDynamicSharedMemorySize, SMEM_LSTM);
    cudaFuncSetAttribute(k_mma_proj, cudaFuncAttributeMaxDynamicSharedMemorySize, SMEM_LIN);
    cudaFuncSetAttribute(k_mma_cls,  cudaFuncAttributeMaxDynamicSharedMemorySize, SMEM_LIN);

    // 0) prep
    k_xTh<<<(SB * 32 + 255) / 256, 256>>>(inp, xT);
    k_prep_w<1><<<(G4 * 32 + 255) / 256, 256>>>(Wih_r, wihr, G4);
    k_prep_w<1><<<(G4 * 32 + 255) / 256, 256>>>(Wih_u, wihu, G4);
    k_prep_w<1><<<(G4 * 32 + 255) / 256, 256>>>(Whh_u, whhu, G4);
    k_prep_w<0><<<(C_ * 32 + 255) / 256, 256>>>(Wc, wc, C_);

    // 1) merged input projections
    {
        dim3 g(32, 14, 2);
        k_mma_proj<<<g, 512, SMEM_LIN>>>(xT,
                                         wihr, xg_r, bih_r, bhh_r,
                                         wihu, xg_u, bih_u, bhh_u);
    }

    // 2) rolling LSTM: 14 sequential FFMA steps (fp32-exact)
    for (int t = 0; t < S_; t++) {
        dim3 g(G4 / 128, B_ / 64);
        const float* hin = (t == 0) ? nullptr : hs + (size_t)(t - 1) * BH;
        const float* cin = (t == 0) ? nullptr : cs + (size_t)(t - 1) * BH;
        k_lstm_step<<<g, 256>>>(hin, Whh_r,
                                xg_r + (size_t)t * B_ * G4, cin,
                                hs + (size_t)t * BH, cs + (size_t)t * BH,
                                (t == 0) ? 1 : 0);
    }

    // 3) init unroll state
    k_h2h<<<(SB * 32 + 255) / 256, 256>>>(hs, hu0);
    cudaMemcpyAsync(cu, cs, sizeof(float) * (size_t)SB * 1024, cudaMemcpyDeviceToDevice, 0);

    // 4) unrolling LSTM: 15 batched fp16 steps (M = nact*256, perfect tiling)
    for (int j = 0; j <= S_; j++) {
        int nact = (15 - j < 14) ? (15 - j) : 14;
        const __half* hin = (j & 1) ? hu1 : hu0;
        __half*       ho  = (j & 1) ? hu0 : hu1;
        int final_t = S_ - j;
        dim3 g(32, nact);
        k_mma_lstm<<<g, 512, SMEM_LSTM>>>(hin, whhu, xg_u, cu, ho, cu, hn, final_t);
    }

    // 5) classifier
    {
        dim3 g(20, 14);
        k_mma_cls<<<g, 512, SMEM_LIN>>>(hn, wc, out, bc, C_);
    }
}

// round 9
// speedup vs baseline: 1.3591x; 1.2123x over previous
#include <cuda_runtime.h>
#include <cuda_fp16.h>
#include <math.h>
#include <stdint.h>

// ---------------- problem constants ----------------
#define B_ 256
#define S_ 14
#define C_ 2513
#define SB 3584          // S_*B_
#define BH 262144        // B_*H_
#define G4 4096          // 4*H_

// ---------------- fp16 mma GEMM config (R5 shape: 128x128, 256 thr) --------
#define STAGE_H   4096                  // halves per operand per stage (128*32)
#define SLOT_H    (2 * STAGE_H)         // A+B per stage = 8192 halves (16KB)
#define NSTAGE    4
#define MAIN_H    (NSTAGE * SLOT_H)     // 32768 halves = 65536 B

// LSTM kernel SMEM: main | xgs(132*128 f32) | cs(36*128 f32) | hsm(128*32 h)
#define XGS_FLOATS (132 * 128)
#define CS_FLOATS  (36 * 128)
#define SMEM_LSTM  (MAIN_H * 2 + XGS_FLOATS * 4 + CS_FLOATS * 4 + 128 * 32 * 2) // 159744
#define SMEM_LIN   (MAIN_H * 2 + 512)   // + bias row = 66048 B

// ---------------- scratch (device globals) ----------------
__device__ __half g_xT [SB * 1024];
__device__ float  g_xg_r[(size_t)SB * G4];
__device__ float  g_xg_u[(size_t)SB * G4];
__device__ float  g_hs [SB * 1024];
__device__ float  g_cs [SB * 1024];
__device__ __half g_hu [2 * SB * 1024];
__device__ float  g_cu [SB * 1024];
__device__ __half g_hn [SB * 1024];
__device__ __half g_wihr[(size_t)G4 * 1024];
__device__ __half g_wihu[(size_t)G4 * 1024];
__device__ __half g_whhu[(size_t)G4 * 1024];
__device__ __half g_wc [(size_t)2560 * 1024];

__device__ __forceinline__ float sigf(float x) { return 1.0f / (1.0f + expf(-x)); }

// logical-k permutation within each 32-k block
__device__ __forceinline__ int perm_l(int p) {
    int b = (p >> 2) & 1, t = p >> 3, j = p & 3;
    return b * 16 + ((j < 2) ? (2 * t + j) : (2 * t + 8 + (j - 2)));
}
__device__ __forceinline__ int inv_l(int l) {
    int b = l >> 4, r = l & 15, hi = r >> 3, t = (r >> 1) & 3, e = r & 1;
    return t * 8 + b * 4 + hi * 2 + e;
}

// ---------------- low-level helpers ----------------
__device__ __forceinline__ uint32_t smaddr(const void* p) {
    uint32_t a;
    asm("{ .reg .u64 t; cvta.to.shared.u64 t, %1; cvt.u32.u64 %0, t; }" : "=r"(a) : "l"(p));
    return a;
}
__device__ __forceinline__ void cp16(uint32_t d, const void* s) {
    asm volatile("cp.async.cg.shared.global [%0], [%1], 16;" :: "r"(d), "l"(s));
}
__device__ __forceinline__ void cp16z(uint32_t d, const void* s, int sz) {
    asm volatile("cp.async.cg.shared.global [%0], [%1], 16, %2;" :: "r"(d), "l"(s), "r"(sz));
}
__device__ __forceinline__ void cpcommit() { asm volatile("cp.async.commit_group;"); }
template <int N>
__device__ __forceinline__ void cpwait() { asm volatile("cp.async.wait_group %0;" :: "n"(N)); }
__device__ __forceinline__ void mma16(float* d, const uint32_t* a, const uint32_t* b) {
    asm volatile(
        "mma.sync.aligned.m16n8k16.row.col.f32.f16.f16.f32 "
        "{%0,%1,%2,%3},{%4,%5,%6,%7},{%8,%9},{%0,%1,%2,%3};"
        : "+f"(d[0]), "+f"(d[1]), "+f"(d[2]), "+f"(d[3])
        : "r"(a[0]), "r"(a[1]), "r"(a[2]), "r"(a[3]), "r"(b[0]), "r"(b[1]));
}

// ---------------- stage issue (256 threads, 128x32 A + 128x32 B) ----------
template <int EDGE>
__device__ __forceinline__ void stage_issue(
    __half* sm, int slot, const __half* __restrict__ A, const __half* __restrict__ W,
    int m0, int n0, int kt, int Nb, int tid)
{
    __half* dA = sm + slot * SLOT_H;
    __half* dB = dA + STAGE_H;
    const __half* Ap = A + (size_t)m0 * 1024 + kt * 32;
    const __half* Wp = W + (size_t)n0 * 1024 + kt * 32;
#pragma unroll
    for (int i = 0; i < 2; i++) {
        int c = tid + (i << 8);
        int row = c >> 2, c16 = c & 3;
        cp16(smaddr(dA + row * 32 + c16 * 8), Ap + (size_t)row * 1024 + c16 * 8);
        if (EDGE) {
            int ok = (n0 + row < Nb);
            cp16z(smaddr(dB + row * 32 + c16 * 8),
                  Wp + (size_t)(ok ? row : 0) * 1024 + c16 * 8, ok ? 16 : 0);
        } else {
            cp16(smaddr(dB + row * 32 + c16 * 8), Wp + (size_t)row * 1024 + c16 * 8);
        }
    }
    cpcommit();
}

// ---------------- epilogue-operand prefetch (slot s8 of 8) ----------------
__device__ __forceinline__ void prefetch_xgc(
    float* xgs, float* cs, const float* __restrict__ xg,
    const float* __restrict__ Cin, int m0, int n0, int s8, int tid)
{
    int base = s8 * 16;
#pragma unroll
    for (int i = 0; i < 2; i++) {
        int unit = tid * 2 + i;                 // 0..511
        int row = base + (unit >> 5), ch = unit & 31;
        cp16(smaddr(xgs + row * 132 + ch * 4),
             xg + (size_t)(m0 + row) * G4 + n0 + ch * 4);
    }
    if (tid < 128) {
        int row = base + (tid >> 3), ch = tid & 7;
        cp16(smaddr(cs + row * 36 + ch * 4),
             Cin + (size_t)(m0 + row) * 1024 + (n0 >> 2) + ch * 4);
    }
}

// ---------------- stage compute: 64x32 warp tile, 32 MMAs -----------------
__device__ __forceinline__ void stage_compute(
    const __half* sm, int slot, int wm, int wn, int g, int tig, float acc[4][4][4])
{
    const __half* bA = sm + slot * SLOT_H + (size_t)(wm * 64 + g) * 32 + tig * 8;
    const __half* bB = sm + slot * SLOT_H + STAGE_H + (size_t)(wn * 32 + g) * 32 + tig * 8;
    uint4 bq[4];
#pragma unroll
    for (int ni = 0; ni < 4; ni++)
        bq[ni] = *(const uint4*)(bB + ni * 8 * 32);
#pragma unroll
    for (int mi = 0; mi < 4; mi++) {
        uint4 alo = *(const uint4*)(bA + mi * 16 * 32);
        uint4 ahi = *(const uint4*)(bA + (mi * 16 + 8) * 32);
        uint32_t af0[4] = {alo.x, ahi.x, alo.y, ahi.y};
        uint32_t af1[4] = {alo.z, ahi.z, alo.w, ahi.w};
#pragma unroll
        for (int ni = 0; ni < 4; ni++) {
            uint32_t bf0[2] = {bq[ni].x, bq[ni].y};
            uint32_t bf1[2] = {bq[ni].z, bq[ni].w};
            mma16(acc[mi][ni], af0, bf0);
            mma16(acc[mi][ni], af1, bf1);
        }
    }
}

// ---------------- generic K=1024 mainloop (proj/cls) ----------------------
template <int EDGE>
__device__ __forceinline__ void run_mainloop(
    __half* sm, const __half* __restrict__ A, const __half* __restrict__ W,
    int m0, int n0, int Nb, float acc[4][4][4],
    int tid, int wm, int wn, int g, int tig)
{
    stage_issue<EDGE>(sm, 0, A, W, m0, n0, 0, Nb, tid);
    stage_issue<EDGE>(sm, 1, A, W, m0, n0, 1, Nb, tid);
    stage_issue<EDGE>(sm, 2, A, W, m0, n0, 2, Nb, tid);
#pragma unroll 1
    for (int kt = 0; kt < 32; kt++) {
        int slot = kt & 3;
        if (kt < 30)       cpwait<2>();
        else if (kt == 30) cpwait<1>();
        else               cpwait<0>();
        __syncthreads();
        if (kt + 3 < 32) stage_issue<EDGE>(sm, (kt + 3) & 3, A, W, m0, n0, kt + 3, Nb, tid);
        stage_compute(sm, slot, wm, wn, g, tig, acc);
    }
}

// ---------------- fused tensor-core LSTM step -----------------------------
__global__ void __launch_bounds__(256, 1) k_mma_lstm(
    const __half* __restrict__ Hin, const __half* __restrict__ Whh,
    const float* __restrict__ xg, const float* __restrict__ Cin,
    __half* __restrict__ Hout, float* __restrict__ Cout,
    __half* __restrict__ Hfin, int final_t)
{
    extern __shared__ __half sm[];
    float*  xgs = (float*)(sm + MAIN_H);
    float*  cs  = xgs + XGS_FLOATS;
    __half* hsm = (__half*)(cs + CS_FLOATS);
    const int tid = threadIdx.x, lane = tid & 31, wid = tid >> 5;
    const int wm = wid & 1, wn = wid >> 1, g = lane >> 2, tig = lane & 3;
    const int m0 = blockIdx.y * 128, n0 = blockIdx.x * 128;

    float acc[4][4][4];
#pragma unroll
    for (int a = 0; a < 4; a++)
#pragma unroll
        for (int b = 0; b < 4; b++)
#pragma unroll
            for (int c = 0; c < 4; c++) acc[a][b][c] = 0.f;

    // mainloop with epilogue-operand prefetch piggybacked on the last 8 chunks
    stage_issue<0>(sm, 0, Hin, Whh, m0, n0, 0, 0x7fffffff, tid);
    stage_issue<0>(sm, 1, Hin, Whh, m0, n0, 1, 0x7fffffff, tid);
    stage_issue<0>(sm, 2, Hin, Whh, m0, n0, 2, 0x7fffffff, tid);
#pragma unroll 1
    for (int kt = 0; kt < 32; kt++) {
        int slot = kt & 3;
        if (kt < 30)       cpwait<2>();
        else if (kt == 30) cpwait<1>();
        else               cpwait<0>();
        __syncthreads();
        if (kt + 3 < 32) {
            int kt2 = kt + 3;
            if (kt2 >= 24) prefetch_xgc(xgs, cs, xg, Cin, m0, n0, kt2 - 24, tid);
            stage_issue<0>(sm, kt2 & 3, Hin, Whh, m0, n0, kt2, 0x7fffffff, tid);
        }
        stage_compute(sm, slot, wm, wn, g, tig, acc);
    }
    // all cp.async groups drained at kt=31 (cpwait<0> + syncthreads): xgs/cs valid

#pragma unroll
    for (int mi = 0; mi < 4; mi++) {
        const int R0 = m0 + wm * 64 + mi * 16;
#pragma unroll
        for (int ni = 0; ni < 4; ni++) {
            const int V0 = n0 + wn * 32 + ni * 8;
            float c0 = acc[mi][ni][0], c1 = acc[mi][ni][1];
            float c2 = acc[mi][ni][2], c3 = acc[mi][ni][3];
            int p = tig & 1;
            float x = p ? c0 : c2, y = p ? c1 : c3;
            float sx = __shfl_xor_sync(0xffffffffu, x, 1);
            float sy = __shfl_xor_sync(0xffffffffu, y, 1);
            float pi, pf, pg, po; int row;
            if (!p) { pi = c0; pf = c1; pg = sx; po = sy; row = R0 + g; }
            else    { pi = sx; pf = sy; pg = c2; po = c3; row = R0 + g + 8; }
            int u  = (V0 >> 2) + (tig >> 1);
            int lr = row - m0;
            int lv = (u << 2) - n0;
            int ul = u - (n0 >> 2);
            float4 xv = *(const float4*)&xgs[lr * 132 + lv];
            float ci = cs[lr * 36 + ul];
            float cn = sigf(pf + xv.y) * ci + sigf(pi + xv.x) * tanhf(pg + xv.z);
            float hv = sigf(po + xv.w) * tanhf(cn);
            cs[lr * 36 + ul] = cn;
            hsm[lr * 32 + inv_l(ul)] = __float2half_rn(hv);
        }
    }
    __syncthreads();
    // coalesced h store: 128 rows x 64B (permuted fp16 layout)
    {
        int r = tid >> 1, seg = tid & 1;
        int m = m0 + r;
        const uint4* src = (const uint4*)(hsm + r * 32 + seg * 16);
        uint4 a = src[0], b = src[1];
        __half* gd = Hout + (size_t)m * 1024 + (n0 >> 2) + seg * 16;
        ((uint4*)gd)[0] = a; ((uint4*)gd)[1] = b;
        if ((m >> 8) == final_t) {
            __half* fd = Hfin + (size_t)m * 1024 + (n0 >> 2) + seg * 16;
            ((uint4*)fd)[0] = a; ((uint4*)fd)[1] = b;
        }
    }
    // coalesced C store: 128 rows x 128B
#pragma unroll
    for (int i = 0; i < 4; i++) {
        int unit = tid + (i << 8);          // 0..1023 float4 units
        int r = unit >> 3, ch = unit & 7;
        *(float4*)&Cout[(size_t)(m0 + r) * 1024 + (n0 >> 2) + ch * 4] =
            *(const float4*)&cs[r * 36 + ch * 4];
    }
}

// ---------------- tensor-core linear (proj MODE=1 / cls MODE=0) -----------
template <int MODE>
__global__ void __launch_bounds__(256, 1) k_mma_lin(
    const __half* __restrict__ A, const __half* __restrict__ W,
    float* __restrict__ Out, const float* __restrict__ b0,
    const float* __restrict__ b1, int N)
{
    extern __shared__ __half sm[];
    float* biasS = (float*)(sm + MAIN_H);
    const int tid = threadIdx.x, lane = tid & 31, wid = tid >> 5;
    const int wm = wid & 1, wn = wid >> 1, g = lane >> 2, tig = lane & 3;
    const int m0 = blockIdx.y * 128, n0 = blockIdx.x * 128;

    if (tid < 128) {
        int np = n0 + tid;
        float bv = 0.f;
        if (MODE == 1) { int wr = ((np & 3) << 10) | (np >> 2); bv = b0[wr] + b1[wr]; }
        else if (np < N) bv = b0[np];
        biasS[tid] = bv;
    }

    float acc[4][4][4];
#pragma unroll
    for (int a = 0; a < 4; a++)
#pragma unroll
        for (int b = 0; b < 4; b++)
#pragma unroll
            for (int c = 0; c < 4; c++) acc[a][b][c] = 0.f;

    run_mainloop<(MODE == 0) ? 1 : 0>(sm, A, W, m0, n0, MODE ? 0x7fffffff : N,
                                      acc, tid, wm, wn, g, tig);

#pragma unroll
    for (int mi = 0; mi < 4; mi++) {
        const int R0 = m0 + wm * 64 + mi * 16;
#pragma unroll
        for (int ni = 0; ni < 4; ni++) {
            const int v = n0 + wn * 32 + ni * 8 + 2 * tig;
            const float bA0 = biasS[v - n0], bA1 = biasS[v - n0 + 1];
            const int r1 = R0 + g, r2 = R0 + g + 8;
            if (MODE == 1) {
                float2 s1 = make_float2(acc[mi][ni][0] + bA0, acc[mi][ni][1] + bA1);
                float2 s2 = make_float2(acc[mi][ni][2] + bA0, acc[mi][ni][3] + bA1);
                *(float2*)(Out + (size_t)r1 * G4 + v) = s1;
                *(float2*)(Out + (size_t)r2 * G4 + v) = s2;
            } else {
                int or1 = (r1 & 255) * S_ + (r1 >> 8);
                int or2 = (r2 & 255) * S_ + (r2 >> 8);
                if (v < N) {
                    Out[(size_t)or1 * N + v] = acc[mi][ni][0] + bA0;
                    Out[(size_t)or2 * N + v] = acc[mi][ni][2] + bA0;
                }
                if (v + 1 < N) {
                    Out[(size_t)or1 * N + v + 1] = acc[mi][ni][1] + bA1;
                    Out[(size_t)or2 * N + v + 1] = acc[mi][ni][3] + bA1;
                }
            }
        }
    }
}

// ---------------- prep kernels (fp32 -> fp16 + k-permute) ------------------
template <int REMAP>
__global__ void k_prep_w(const float* __restrict__ in, __half* __restrict__ out, int rows) {
    int idx = blockIdx.x * blockDim.x + threadIdx.x;
    if (idx >= rows * 32) return;
    int r = idx >> 5, b32 = idx & 31;
    int wr = REMAP ? (((r & 3) << 10) | (r >> 2)) : r;
    const float* src = in + (size_t)wr * 1024 + b32 * 32;
    float v[32];
#pragma unroll
    for (int i = 0; i < 8; i++) *(float4*)&v[i * 4] = *(const float4*)(src + i * 4);
    __half h[32];
#pragma unroll
    for (int p = 0; p < 32; p++) h[p] = __float2half_rn(v[perm_l(p)]);
    uint4* dst = (uint4*)(out + (size_t)r * 1024 + b32 * 32);
#pragma unroll
    for (int i = 0; i < 4; i++) dst[i] = ((const uint4*)h)[i];
}

__global__ void k_xTh(const float* __restrict__ in, __half* __restrict__ out) {
    int idx = blockIdx.x * blockDim.x + threadIdx.x;
    if (idx >= SB * 32) return;
    int r = idx >> 5, b32 = idx & 31;
    int b = r % B_, s = r / B_;
    const float* src = in + (size_t)(b * S_ + s) * 1024 + b32 * 32;
    float v[32];
#pragma unroll
    for (int i = 0; i < 8; i++) *(float4*)&v[i * 4] = *(const float4*)(src + i * 4);
    __half h[32];
#pragma unroll
    for (int p = 0; p < 32; p++) h[p] = __float2half_rn(v[perm_l(p)]);
    uint4* dst = (uint4*)(out + (size_t)r * 1024 + b32 * 32);
#pragma unroll
    for (int i = 0; i < 4; i++) dst[i] = ((const uint4*)h)[i];
}

__global__ void k_h2h(const float* __restrict__ in, __half* __restrict__ out) {
    int idx = blockIdx.x * blockDim.x + threadIdx.x;
    if (idx >= SB * 32) return;
    int r = idx >> 5, b32 = idx & 31;
    const float* src = in + (size_t)r * 1024 + b32 * 32;
    float v[32];
#pragma unroll
    for (int i = 0; i < 8; i++) *(float4*)&v[i * 4] = *(const float4*)(src + i * 4);
    __half h[32];
#pragma unroll
    for (int p = 0; p < 32; p++) h[p] = __float2half_rn(v[perm_l(p)]);
    uint4* dst = (uint4*)(out + (size_t)r * 1024 + b32 * 32);
#pragma unroll
    for (int i = 0; i < 4; i++) dst[i] = ((const uint4*)h)[i];
}

// ---------------- FFMA rolling LSTM step (fp32-exact, M=256) ---------------
__global__ void __launch_bounds__(256) k_lstm_step(
    const float* __restrict__ Hin, const float* __restrict__ Whh,
    const float* __restrict__ xg, const float* __restrict__ Cin,
    float* __restrict__ Hout, float* __restrict__ Cout, int zeroInit)
{
    constexpr int BM = 64, TM = 4;
    __shared__ float As[16][BM + 4];
    __shared__ float Ws[16][132];
    const int tid = threadIdx.x;
    const int tx = tid & 15, ty = tid >> 4;
    const int m0 = blockIdx.y * BM;
    const int n0 = blockIdx.x * 128;

    float acc[TM][8];
#pragma unroll
    for (int i = 0; i < TM; i++)
#pragma unroll
        for (int j = 0; j < 8; j++) acc[i][j] = 0.f;

    if (!zeroInit) {
        const int lr = tid >> 2;
        const int lk = (tid & 3) << 2;
        for (int kt = 0; kt < 1024; kt += 16) {
            {
                int row = lr;
                float4 v = *(const float4*)&Hin[(size_t)(m0 + row) * 1024 + kt + lk];
                As[lk + 0][row] = v.x; As[lk + 1][row] = v.y;
                As[lk + 2][row] = v.z; As[lk + 3][row] = v.w;
            }
#pragma unroll
            for (int r = 0; r < 2; r++) {
                int wr2 = lr + r * 64;
                int np = n0 + wr2;
                int wrow = ((np & 3) << 10) + (np >> 2);
                float4 v = *(const float4*)&Whh[(size_t)wrow * 1024 + kt + lk];
                Ws[lk + 0][wr2] = v.x; Ws[lk + 1][wr2] = v.y;
                Ws[lk + 2][wr2] = v.z; Ws[lk + 3][wr2] = v.w;
            }
            __syncthreads();
#pragma unroll
            for (int k = 0; k < 16; k++) {
                float a[TM], wv[8];
#pragma unroll
                for (int i = 0; i < TM; i++) a[i] = As[k][ty * TM + i];
#pragma unroll
                for (int j = 0; j < 8; j++) wv[j] = Ws[k][tx * 8 + j];
#pragma unroll
                for (int i = 0; i < TM; i++)
#pragma unroll
                    for (int j = 0; j < 8; j++) acc[i][j] = fmaf(a[i], wv[j], acc[i][j]);
            }
            __syncthreads();
        }
    }

    const int u0 = (n0 + tx * 8) >> 2;
#pragma unroll
    for (int i = 0; i < TM; i++) {
        int m = m0 + ty * TM + i;
        const float* xr = xg + (size_t)m * G4;
#pragma unroll
        for (int uu = 0; uu < 2; uu++) {
            int u = u0 + uu;
            float4 xv = *(const float4*)&xr[(size_t)u * 4];
            float pi = acc[i][uu * 4 + 0] + xv.x;
            float pf = acc[i][uu * 4 + 1] + xv.y;
            float pg = acc[i][uu * 4 + 2] + xv.z;
            float po = acc[i][uu * 4 + 3] + xv.w;
            float c  = zeroInit ? 0.f : Cin[(size_t)m * 1024 + u];
            float c2 = sigf(pf) * c + sigf(pi) * tanhf(pg);
            float h2 = sigf(po) * tanhf(c2);
            Hout[(size_t)m * 1024 + u] = h2;
            Cout[(size_t)m * 1024 + u] = c2;
        }
    }
}

// ---------------- host orchestration ----------------
extern "C" void kernel_launch(void* const* d_in, const int* in_sizes, int n_in,
                              void* d_out, int out_size) {
    (void)in_sizes; (void)n_in; (void)out_size;
    const float* inp   = (const float*)d_in[0];
    const float* Wih_r = (const float*)d_in[1];
    const float* Whh_r = (const float*)d_in[2];
    const float* bih_r = (const float*)d_in[3];
    const float* bhh_r = (const float*)d_in[4];
    const float* Wih_u = (const float*)d_in[5];
    const float* Whh_u = (const float*)d_in[6];
    const float* bih_u = (const float*)d_in[7];
    const float* bhh_u = (const float*)d_in[8];
    const float* Wc    = (const float*)d_in[9];
    const float* bc    = (const float*)d_in[10];
    float* out = (float*)d_out;

    __half *xT, *hu, *hn, *wihr, *wihu, *whhu, *wc;
    float *xg_r, *xg_u, *hs, *cs, *cu;
    cudaGetSymbolAddress((void**)&xT,   g_xT);
    cudaGetSymbolAddress((void**)&xg_r, g_xg_r);
    cudaGetSymbolAddress((void**)&xg_u, g_xg_u);
    cudaGetSymbolAddress((void**)&hs,   g_hs);
    cudaGetSymbolAddress((void**)&cs,   g_cs);
    cudaGetSymbolAddress((void**)&hu,   g_hu);
    cudaGetSymbolAddress((void**)&cu,   g_cu);
    cudaGetSymbolAddress((void**)&hn,   g_hn);
    cudaGetSymbolAddress((void**)&wihr, g_wihr);
    cudaGetSymbolAddress((void**)&wihu, g_wihu);
    cudaGetSymbolAddress((void**)&whhu, g_whhu);
    cudaGetSymbolAddress((void**)&wc,   g_wc);
    __half* hu0 = hu;
    __half* hu1 = hu + (size_t)SB * 1024;

    cudaFuncSetAttribute(k_mma_lstm,   cudaFuncAttributeMaxDynamicSharedMemorySize, SMEM_LSTM);
    cudaFuncSetAttribute(k_mma_lin<1>, cudaFuncAttributeMaxDynamicSharedMemorySize, SMEM_LIN);
    cudaFuncSetAttribute(k_mma_lin<0>, cudaFuncAttributeMaxDynamicSharedMemorySize, SMEM_LIN);

    // 0) prep
    k_xTh<<<(SB * 32 + 255) / 256, 256>>>(inp, xT);
    k_prep_w<1><<<(G4 * 32 + 255) / 256, 256>>>(Wih_r, wihr, G4);
    k_prep_w<1><<<(G4 * 32 + 255) / 256, 256>>>(Wih_u, wihu, G4);
    k_prep_w<1><<<(G4 * 32 + 255) / 256, 256>>>(Whh_u, whhu, G4);
    k_prep_w<0><<<(C_ * 32 + 255) / 256, 256>>>(Wc, wc, C_);

    // 1) input projections -> gate-interleaved fp32 xg
    {
        dim3 g(G4 / 128, SB / 128);
        k_mma_lin<1><<<g, 256, SMEM_LIN>>>(xT, wihr, xg_r, bih_r, bhh_r, G4);
        k_mma_lin<1><<<g, 256, SMEM_LIN>>>(xT, wihu, xg_u, bih_u, bhh_u, G4);
    }

    // 2) rolling LSTM: 14 sequential FFMA steps (fp32-exact)
    for (int t = 0; t < S_; t++) {
        dim3 g(G4 / 128, B_ / 64);
        const float* hin = (t == 0) ? nullptr : hs + (size_t)(t - 1) * BH;
        const float* cin = (t == 0) ? nullptr : cs + (size_t)(t - 1) * BH;
        k_lstm_step<<<g, 256>>>(hin, Whh_r,
                                xg_r + (size_t)t * B_ * G4, cin,
                                hs + (size_t)t * BH, cs + (size_t)t * BH,
                                (t == 0) ? 1 : 0);
    }

    // 3) init unroll state
    k_h2h<<<(SB * 32 + 255) / 256, 256>>>(hs, hu0);
    cudaMemcpyAsync(cu, cs, sizeof(float) * (size_t)SB * 1024, cudaMemcpyDeviceToDevice, 0);

    // 4) unrolling LSTM: 15 batched fp16 steps (128x128 tiles, R5 grid)
    for (int j = 0; j <= S_; j++) {
        int nact = (15 - j < 14) ? (15 - j) : 14;
        const __half* hin = (j & 1) ? hu1 : hu0;
        __half*       ho  = (j & 1) ? hu0 : hu1;
        int final_t = S_ - j;
        dim3 g(G4 / 128, nact * 2);
        k_mma_lstm<<<g, 256, SMEM_LSTM>>>(hin, whhu, xg_u, cu, ho, cu, hn, final_t);
    }

    // 5) classifier
    {
        dim3 g((C_ + 127) / 128, SB / 128);
        k_mma_lin<0><<<g, 256, SMEM_LIN>>>(hn, wc, out, bc, nullptr, C_);
    }
}

// round 10
// speedup vs baseline: 1.3847x; 1.0189x over previous
#include <cuda_runtime.h>
#include <cuda_fp16.h>
#include <math.h>
#include <stdint.h>

// ---------------- problem constants ----------------
#define B_ 256
#define S_ 14
#define C_ 2513
#define SB 3584          // S_*B_
#define BH 262144        // B_*H_
#define G4 4096          // 4*H_

// ---------------- fp16 mma GEMM config (128x128, 256 thr, occ 2) ----------
#define STAGE_H   4096                  // halves per operand per stage (128*32)
#define SLOT_H    (2 * STAGE_H)         // A+B per stage = 8192 halves (16KB)
#define NSTAGE    4
#define MAIN_H    (NSTAGE * SLOT_H)     // 32768 halves = 65536 B
#define SMEM_LSTM ((MAIN_H + 128 * 32) * 2)  // + h tile 8KB = 73728 B
#define SMEM_LIN  (MAIN_H * 2 + 512)         // + bias row   = 66048 B

// ---------------- scratch (device globals) ----------------
__device__ __half g_xT [SB * 1024];
__device__ float  g_xg_r[(size_t)SB * G4];
__device__ float  g_xg_u[(size_t)SB * G4];
__device__ float  g_hs [SB * 1024];
__device__ float  g_cs [SB * 1024];
__device__ __half g_hu [2 * SB * 1024];
__device__ float  g_cu [SB * 1024];
__device__ __half g_hn [SB * 1024];
__device__ __half g_wihr[(size_t)G4 * 1024];
__device__ __half g_wihu[(size_t)G4 * 1024];
__device__ __half g_whhu[(size_t)G4 * 1024];
__device__ __half g_wc [(size_t)2560 * 1024];
__device__ int    g_nopsink;

__device__ __forceinline__ float sigf(float x) { return 1.0f / (1.0f + expf(-x)); }

// logical-k permutation within each 32-k block
__device__ __forceinline__ int perm_l(int p) {
    int b = (p >> 2) & 1, t = p >> 3, j = p & 3;
    return b * 16 + ((j < 2) ? (2 * t + j) : (2 * t + 8 + (j - 2)));
}
__device__ __forceinline__ int inv_l(int l) {
    int b = l >> 4, r = l & 15, hi = r >> 3, t = (r >> 1) & 3, e = r & 1;
    return t * 8 + b * 4 + hi * 2 + e;
}

// ---------------- low-level helpers ----------------
__device__ __forceinline__ uint32_t smaddr(const void* p) {
    uint32_t a;
    asm("{ .reg .u64 t; cvta.to.shared.u64 t, %1; cvt.u32.u64 %0, t; }" : "=r"(a) : "l"(p));
    return a;
}
__device__ __forceinline__ void cp16(uint32_t d, const void* s) {
    asm volatile("cp.async.cg.shared.global [%0], [%1], 16;" :: "r"(d), "l"(s));
}
__device__ __forceinline__ void cp16z(uint32_t d, const void* s, int sz) {
    asm volatile("cp.async.cg.shared.global [%0], [%1], 16, %2;" :: "r"(d), "l"(s), "r"(sz));
}
__device__ __forceinline__ void cpcommit() { asm volatile("cp.async.commit_group;"); }
template <int N>
__device__ __forceinline__ void cpwait() { asm volatile("cp.async.wait_group %0;" :: "n"(N)); }
__device__ __forceinline__ void mma16(float* d, const uint32_t* a, const uint32_t* b) {
    asm volatile(
        "mma.sync.aligned.m16n8k16.row.col.f32.f16.f16.f32 "
        "{%0,%1,%2,%3},{%4,%5,%6,%7},{%8,%9},{%0,%1,%2,%3};"
        : "+f"(d[0]), "+f"(d[1]), "+f"(d[2]), "+f"(d[3])
        : "r"(a[0]), "r"(a[1]), "r"(a[2]), "r"(a[3]), "r"(b[0]), "r"(b[1]));
}

// ---------------- stage issue (256 threads, 128x32 A + 128x32 B) ----------
template <int EDGE>
__device__ __forceinline__ void stage_issue(
    __half* sm, int slot, const __half* __restrict__ A, const __half* __restrict__ W,
    int m0, int n0, int kt, int Nb, int tid)
{
    __half* dA = sm + slot * SLOT_H;
    __half* dB = dA + STAGE_H;
    const __half* Ap = A + (size_t)m0 * 1024 + kt * 32;
    const __half* Wp = W + (size_t)n0 * 1024 + kt * 32;
#pragma unroll
    for (int i = 0; i < 2; i++) {
        int c = tid + (i << 8);
        int row = c >> 2, c16 = c & 3;
        cp16(smaddr(dA + row * 32 + c16 * 8), Ap + (size_t)row * 1024 + c16 * 8);
        if (EDGE) {
            int ok = (n0 + row < Nb);
            cp16z(smaddr(dB + row * 32 + c16 * 8),
                  Wp + (size_t)(ok ? row : 0) * 1024 + c16 * 8, ok ? 16 : 0);
        } else {
            cp16(smaddr(dB + row * 32 + c16 * 8), Wp + (size_t)row * 1024 + c16 * 8);
        }
    }
    cpcommit();
}

// ---------------- stage compute: 64x32 warp tile, 32 MMAs ------------------
// Same-accumulator MMAs are 8 apart (was back-to-back): B frags hoisted,
// A loaded per mi-pair, h-pass-major issue order.
__device__ __forceinline__ void stage_compute(
    const __half* sm, int slot, int wm, int wn, int g, int tig, float acc[4][4][4])
{
    const __half* bA = sm + slot * SLOT_H + (size_t)(wm * 64 + g) * 32 + tig * 8;
    const __half* bB = sm + slot * SLOT_H + STAGE_H + (size_t)(wn * 32 + g) * 32 + tig * 8;
    uint4 bq[4];
#pragma unroll
    for (int ni = 0; ni < 4; ni++)
        bq[ni] = *(const uint4*)(bB + ni * 8 * 32);
#pragma unroll
    for (int mp = 0; mp < 2; mp++) {
        const int m0i = mp * 2, m1i = mp * 2 + 1;
        uint4 alo0 = *(const uint4*)(bA + m0i * 16 * 32);
        uint4 ahi0 = *(const uint4*)(bA + (m0i * 16 + 8) * 32);
        uint4 alo1 = *(const uint4*)(bA + m1i * 16 * 32);
        uint4 ahi1 = *(const uint4*)(bA + (m1i * 16 + 8) * 32);
        uint32_t a00[4] = {alo0.x, ahi0.x, alo0.y, ahi0.y};
        uint32_t a01[4] = {alo0.z, ahi0.z, alo0.w, ahi0.w};
        uint32_t a10[4] = {alo1.x, ahi1.x, alo1.y, ahi1.y};
        uint32_t a11[4] = {alo1.z, ahi1.z, alo1.w, ahi1.w};
#pragma unroll
        for (int ni = 0; ni < 4; ni++) {
            uint32_t bf0[2] = {bq[ni].x, bq[ni].y};
            mma16(acc[m0i][ni], a00, bf0);
        }
#pragma unroll
        for (int ni = 0; ni < 4; ni++) {
            uint32_t bf0[2] = {bq[ni].x, bq[ni].y};
            mma16(acc[m1i][ni], a10, bf0);
        }
#pragma unroll
        for (int ni = 0; ni < 4; ni++) {
            uint32_t bf1[2] = {bq[ni].z, bq[ni].w};
            mma16(acc[m0i][ni], a01, bf1);
        }
#pragma unroll
        for (int ni = 0; ni < 4; ni++) {
            uint32_t bf1[2] = {bq[ni].z, bq[ni].w};
            mma16(acc[m1i][ni], a11, bf1);
        }
    }
}

// ---------------- full K=1024 mainloop (4-stage, 1 sync/iter) --------------
template <int EDGE>
__device__ __forceinline__ void run_mainloop(
    __half* sm, const __half* __restrict__ A, const __half* __restrict__ W,
    int m0, int n0, int Nb, float acc[4][4][4],
    int tid, int wm, int wn, int g, int tig)
{
    stage_issue<EDGE>(sm, 0, A, W, m0, n0, 0, Nb, tid);
    stage_issue<EDGE>(sm, 1, A, W, m0, n0, 1, Nb, tid);
    stage_issue<EDGE>(sm, 2, A, W, m0, n0, 2, Nb, tid);
#pragma unroll 1
    for (int kt = 0; kt < 32; kt++) {
        int slot = kt & 3;
        if (kt < 30)       cpwait<2>();
        else if (kt == 30) cpwait<1>();
        else               cpwait<0>();
        __syncthreads();
        if (kt + 3 < 32) stage_issue<EDGE>(sm, (kt + 3) & 3, A, W, m0, n0, kt + 3, Nb, tid);
        stage_compute(sm, slot, wm, wn, g, tig, acc);
    }
}

// ---------------- fused tensor-core LSTM step ------------------------------
__global__ void __launch_bounds__(256, 2) k_mma_lstm(
    const __half* __restrict__ Hin, const __half* __restrict__ Whh,
    const float* __restrict__ xg, const float* __restrict__ Cin,
    __half* __restrict__ Hout, float* __restrict__ Cout,
    __half* __restrict__ Hfin, int final_t)
{
    extern __shared__ __half sm[];
    __half* hsm = sm + MAIN_H;
    const int tid = threadIdx.x, lane = tid & 31, wid = tid >> 5;
    const int wm = wid & 1, wn = wid >> 1, g = lane >> 2, tig = lane & 3;
    const int m0 = blockIdx.y * 128, n0 = blockIdx.x * 128;

    float acc[4][4][4];
#pragma unroll
    for (int a = 0; a < 4; a++)
#pragma unroll
        for (int b = 0; b < 4; b++)
#pragma unroll
            for (int c = 0; c < 4; c++) acc[a][b][c] = 0.f;

    run_mainloop<0>(sm, Hin, Whh, m0, n0, 0x7fffffff, acc, tid, wm, wn, g, tig);

#pragma unroll
    for (int mi = 0; mi < 4; mi++) {
        const int R0 = m0 + wm * 64 + mi * 16;
#pragma unroll
        for (int ni = 0; ni < 4; ni++) {
            const int V0 = n0 + wn * 32 + ni * 8;
            float c0 = acc[mi][ni][0], c1 = acc[mi][ni][1];
            float c2 = acc[mi][ni][2], c3 = acc[mi][ni][3];
            int p = tig & 1;
            float x = p ? c0 : c2, y = p ? c1 : c3;
            float sx = __shfl_xor_sync(0xffffffffu, x, 1);
            float sy = __shfl_xor_sync(0xffffffffu, y, 1);
            float pi, pf, pg, po; int row;
            if (!p) { pi = c0; pf = c1; pg = sx; po = sy; row = R0 + g; }
            else    { pi = sx; pf = sy; pg = c2; po = c3; row = R0 + g + 8; }
            int u = (V0 >> 2) + (tig >> 1);
            float4 xv = *(const float4*)(xg + (size_t)row * G4 + u * 4);
            float ci = Cin[(size_t)row * 1024 + u];
            float cn = sigf(pf + xv.y) * ci + sigf(pi + xv.x) * tanhf(pg + xv.z);
            float hv = sigf(po + xv.w) * tanhf(cn);
            Cout[(size_t)row * 1024 + u] = cn;
            int ul = u - (n0 >> 2);
            hsm[(row - m0) * 32 + inv_l(ul)] = __float2half_rn(hv);
        }
    }
    __syncthreads();
    // coalesced h store: 128 rows x 64B (permuted fp16 layout)
    {
        int r = tid >> 1, seg = tid & 1;
        int m = m0 + r;
        const uint4* src = (const uint4*)(hsm + r * 32 + seg * 16);
        uint4 a = src[0], b = src[1];
        __half* gd = Hout + (size_t)m * 1024 + (n0 >> 2) + seg * 16;
        ((uint4*)gd)[0] = a; ((uint4*)gd)[1] = b;
        if ((m >> 8) == final_t) {
            __half* fd = Hfin + (size_t)m * 1024 + (n0 >> 2) + seg * 16;
            ((uint4*)fd)[0] = a; ((uint4*)fd)[1] = b;
        }
    }
}

// ---------------- tensor-core linear (proj MODE=1 / cls MODE=0) ------------
template <int MODE>
__global__ void __launch_bounds__(256, 2) k_mma_lin(
    const __half* __restrict__ A, const __half* __restrict__ W,
    float* __restrict__ Out, const float* __restrict__ b0,
    const float* __restrict__ b1, int N)
{
    extern __shared__ __half sm[];
    float* biasS = (float*)(sm + MAIN_H);
    const int tid = threadIdx.x, lane = tid & 31, wid = tid >> 5;
    const int wm = wid & 1, wn = wid >> 1, g = lane >> 2, tig = lane & 3;
    const int m0 = blockIdx.y * 128, n0 = blockIdx.x * 128;

    if (tid < 128) {
        int np = n0 + tid;
        float bv = 0.f;
        if (MODE == 1) { int wr = ((np & 3) << 10) | (np >> 2); bv = b0[wr] + b1[wr]; }
        else if (np < N) bv = b0[np];
        biasS[tid] = bv;
    }

    float acc[4][4][4];
#pragma unroll
    for (int a = 0; a < 4; a++)
#pragma unroll
        for (int b = 0; b < 4; b++)
#pragma unroll
            for (int c = 0; c < 4; c++) acc[a][b][c] = 0.f;

    run_mainloop<(MODE == 0) ? 1 : 0>(sm, A, W, m0, n0, MODE ? 0x7fffffff : N,
                                      acc, tid, wm, wn, g, tig);

#pragma unroll
    for (int mi = 0; mi < 4; mi++) {
        const int R0 = m0 + wm * 64 + mi * 16;
#pragma unroll
        for (int ni = 0; ni < 4; ni++) {
            const int v = n0 + wn * 32 + ni * 8 + 2 * tig;
            const float bA0 = biasS[v - n0], bA1 = biasS[v - n0 + 1];
            const int r1 = R0 + g, r2 = R0 + g + 8;
            if (MODE == 1) {
                float2 s1 = make_float2(acc[mi][ni][0] + bA0, acc[mi][ni][1] + bA1);
                float2 s2 = make_float2(acc[mi][ni][2] + bA0, acc[mi][ni][3] + bA1);
                *(float2*)(Out + (size_t)r1 * G4 + v) = s1;
                *(float2*)(Out + (size_t)r2 * G4 + v) = s2;
            } else {
                int or1 = (r1 & 255) * S_ + (r1 >> 8);
                int or2 = (r2 & 255) * S_ + (r2 >> 8);
                if (v < N) {
                    Out[(size_t)or1 * N + v] = acc[mi][ni][0] + bA0;
                    Out[(size_t)or2 * N + v] = acc[mi][ni][2] + bA0;
                }
                if (v + 1 < N) {
                    Out[(size_t)or1 * N + v + 1] = acc[mi][ni][1] + bA1;
                    Out[(size_t)or2 * N + v + 1] = acc[mi][ni][3] + bA1;
                }
            }
        }
    }
}

// ---------------- merged prep kernel (fp32 -> fp16 + k-permute) ------------
// Segments: [0, SB*32) xT transpose; then wihr / wihu / whhu (REMAP);
// then wc (no remap). One 32-half output block per thread.
#define PREP_XT   (SB * 32)
#define PREP_W    (G4 * 32)
#define PREP_WC   (C_ * 32)
#define PREP_TOT  (PREP_XT + 3 * PREP_W + PREP_WC)

__global__ void k_prep_all(
    const float* __restrict__ inp,
    const float* __restrict__ Wih_r, const float* __restrict__ Wih_u,
    const float* __restrict__ Whh_u, const float* __restrict__ Wc,
    __half* __restrict__ xT, __half* __restrict__ wihr, __half* __restrict__ wihu,
    __half* __restrict__ whhu, __half* __restrict__ wc)
{
    int idx = blockIdx.x * blockDim.x + threadIdx.x;
    if (idx >= PREP_TOT) return;
    const float* src;
    __half* dstbase;
    int r, b32;
    if (idx < PREP_XT) {
        r = idx >> 5; b32 = idx & 31;
        int b = r % B_, s = r / B_;
        src = inp + (size_t)(b * S_ + s) * 1024 + b32 * 32;
        dstbase = xT;
    } else {
        int t = idx - PREP_XT;
        int seg = t / PREP_W;                 // 0,1,2 -> weights; 3 -> wc region
        if (seg < 3) {
            int u = t - seg * PREP_W;
            r = u >> 5; b32 = u & 31;
            int wr = ((r & 3) << 10) | (r >> 2);
            const float* W = (seg == 0) ? Wih_r : (seg == 1) ? Wih_u : Whh_u;
            src = W + (size_t)wr * 1024 + b32 * 32;
            dstbase = (seg == 0) ? wihr : (seg == 1) ? wihu : whhu;
        } else {
            int u = t - 3 * PREP_W;
            r = u >> 5; b32 = u & 31;
            src = Wc + (size_t)r * 1024 + b32 * 32;
            dstbase = wc;
        }
    }
    float v[32];
#pragma unroll
    for (int i = 0; i < 8; i++) *(float4*)&v[i * 4] = *(const float4*)(src + i * 4);
    __half h[32];
#pragma unroll
    for (int p = 0; p < 32; p++) h[p] = __float2half_rn(v[perm_l(p)]);
    uint4* dst = (uint4*)(dstbase + (size_t)r * 1024 + b32 * 32);
#pragma unroll
    for (int i = 0; i < 4; i++) dst[i] = ((const uint4*)h)[i];
}

// filler so ncu -s 5 captures the projection GEMM
__global__ void k_nop() {
    if (threadIdx.x == 0 && blockIdx.x == 12345) g_nopsink = 1;
}

// h (fp32 logical) -> fp16 permuted
__global__ void k_h2h(const float* __restrict__ in, __half* __restrict__ out) {
    int idx = blockIdx.x * blockDim.x + threadIdx.x;
    if (idx >= SB * 32) return;
    int r = idx >> 5, b32 = idx & 31;
    const float* src = in + (size_t)r * 1024 + b32 * 32;
    float v[32];
#pragma unroll
    for (int i = 0; i < 8; i++) *(float4*)&v[i * 4] = *(const float4*)(src + i * 4);
    __half h[32];
#pragma unroll
    for (int p = 0; p < 32; p++) h[p] = __float2half_rn(v[perm_l(p)]);
    uint4* dst = (uint4*)(out + (size_t)r * 1024 + b32 * 32);
#pragma unroll
    for (int i = 0; i < 4; i++) dst[i] = ((const uint4*)h)[i];
}

// ---------------- FFMA rolling LSTM step (fp32-exact, M=256) ---------------
__global__ void __launch_bounds__(256) k_lstm_step(
    const float* __restrict__ Hin, const float* __restrict__ Whh,
    const float* __restrict__ xg, const float* __restrict__ Cin,
    float* __restrict__ Hout, float* __restrict__ Cout, int zeroInit)
{
    constexpr int BM = 64, TM = 4;
    __shared__ float As[16][BM + 4];
    __shared__ float Ws[16][132];
    const int tid = threadIdx.x;
    const int tx = tid & 15, ty = tid >> 4;
    const int m0 = blockIdx.y * BM;
    const int n0 = blockIdx.x * 128;

    float acc[TM][8];
#pragma unroll
    for (int i = 0; i < TM; i++)
#pragma unroll
        for (int j = 0; j < 8; j++) acc[i][j] = 0.f;

    if (!zeroInit) {
        const int lr = tid >> 2;
        const int lk = (tid & 3) << 2;
        for (int kt = 0; kt < 1024; kt += 16) {
            {
                int row = lr;
                float4 v = *(const float4*)&Hin[(size_t)(m0 + row) * 1024 + kt + lk];
                As[lk + 0][row] = v.x; As[lk + 1][row] = v.y;
                As[lk + 2][row] = v.z; As[lk + 3][row] = v.w;
            }
#pragma unroll
            for (int r = 0; r < 2; r++) {
                int wr2 = lr + r * 64;
                int np = n0 + wr2;
                int wrow = ((np & 3) << 10) + (np >> 2);
                float4 v = *(const float4*)&Whh[(size_t)wrow * 1024 + kt + lk];
                Ws[lk + 0][wr2] = v.x; Ws[lk + 1][wr2] = v.y;
                Ws[lk + 2][wr2] = v.z; Ws[lk + 3][wr2] = v.w;
            }
            __syncthreads();
#pragma unroll
            for (int k = 0; k < 16; k++) {
                float a[TM], wv[8];
#pragma unroll
                for (int i = 0; i < TM; i++) a[i] = As[k][ty * TM + i];
#pragma unroll
                for (int j = 0; j < 8; j++) wv[j] = Ws[k][tx * 8 + j];
#pragma unroll
                for (int i = 0; i < TM; i++)
#pragma unroll
                    for (int j = 0; j < 8; j++) acc[i][j] = fmaf(a[i], wv[j], acc[i][j]);
            }
            __syncthreads();
        }
    }

    const int u0 = (n0 + tx * 8) >> 2;
#pragma unroll
    for (int i = 0; i < TM; i++) {
        int m = m0 + ty * TM + i;
        const float* xr = xg + (size_t)m * G4;
#pragma unroll
        for (int uu = 0; uu < 2; uu++) {
            int u = u0 + uu;
            float4 xv = *(const float4*)&xr[(size_t)u * 4];
            float pi = acc[i][uu * 4 + 0] + xv.x;
            float pf = acc[i][uu * 4 + 1] + xv.y;
            float pg = acc[i][uu * 4 + 2] + xv.z;
            float po = acc[i][uu * 4 + 3] + xv.w;
            float c  = zeroInit ? 0.f : Cin[(size_t)m * 1024 + u];
            float c2 = sigf(pf) * c + sigf(pi) * tanhf(pg);
            float h2 = sigf(po) * tanhf(c2);
            Hout[(size_t)m * 1024 + u] = h2;
            Cout[(size_t)m * 1024 + u] = c2;
        }
    }
}

// ---------------- host orchestration ----------------
extern "C" void kernel_launch(void* const* d_in, const int* in_sizes, int n_in,
                              void* d_out, int out_size) {
    (void)in_sizes; (void)n_in; (void)out_size;
    const float* inp   = (const float*)d_in[0];
    const float* Wih_r = (const float*)d_in[1];
    const float* Whh_r = (const float*)d_in[2];
    const float* bih_r = (const float*)d_in[3];
    const float* bhh_r = (const float*)d_in[4];
    const float* Wih_u = (const float*)d_in[5];
    const float* Whh_u = (const float*)d_in[6];
    const float* bih_u = (const float*)d_in[7];
    const float* bhh_u = (const float*)d_in[8];
    const float* Wc    = (const float*)d_in[9];
    const float* bc    = (const float*)d_in[10];
    float* out = (float*)d_out;

    __half *xT, *hu, *hn, *wihr, *wihu, *whhu, *wc;
    float *xg_r, *xg_u, *hs, *cs, *cu;
    cudaGetSymbolAddress((void**)&xT,   g_xT);
    cudaGetSymbolAddress((void**)&xg_r, g_xg_r);
    cudaGetSymbolAddress((void**)&xg_u, g_xg_u);
    cudaGetSymbolAddress((void**)&hs,   g_hs);
    cudaGetSymbolAddress((void**)&cs,   g_cs);
    cudaGetSymbolAddress((void**)&hu,   g_hu);
    cudaGetSymbolAddress((void**)&cu,   g_cu);
    cudaGetSymbolAddress((void**)&hn,   g_hn);
    cudaGetSymbolAddress((void**)&wihr, g_wihr);
    cudaGetSymbolAddress((void**)&wihu, g_wihu);
    cudaGetSymbolAddress((void**)&whhu, g_whhu);
    cudaGetSymbolAddress((void**)&wc,   g_wc);
    __half* hu0 = hu;
    __half* hu1 = hu + (size_t)SB * 1024;

    cudaFuncSetAttribute(k_mma_lstm,   cudaFuncAttributeMaxDynamicSharedMemorySize, SMEM_LSTM);
    cudaFuncSetAttribute(k_mma_lin<1>, cudaFuncAttributeMaxDynamicSharedMemorySize, SMEM_LIN);
    cudaFuncSetAttribute(k_mma_lin<0>, cudaFuncAttributeMaxDynamicSharedMemorySize, SMEM_LIN);

    // 0) prep (launch 1) + 4 fillers so ncu -s 5 lands on the proj GEMM
    k_prep_all<<<(PREP_TOT + 255) / 256, 256>>>(inp, Wih_r, Wih_u, Whh_u, Wc,
                                                xT, wihr, wihu, whhu, wc);
    k_nop<<<1, 32>>>();
    k_nop<<<1, 32>>>();
    k_nop<<<1, 32>>>();
    k_nop<<<1, 32>>>();

    // 1) input projections (launches 6, 7)
    {
        dim3 g(G4 / 128, SB / 128);
        k_mma_lin<1><<<g, 256, SMEM_LIN>>>(xT, wihr, xg_r, bih_r, bhh_r, G4);
        k_mma_lin<1><<<g, 256, SMEM_LIN>>>(xT, wihu, xg_u, bih_u, bhh_u, G4);
    }

    // 2) rolling LSTM: 14 sequential FFMA steps (fp32-exact)
    for (int t = 0; t < S_; t++) {
        dim3 g(G4 / 128, B_ / 64);
        const float* hin = (t == 0) ? nullptr : hs + (size_t)(t - 1) * BH;
        const float* cin = (t == 0) ? nullptr : cs + (size_t)(t - 1) * BH;
        k_lstm_step<<<g, 256>>>(hin, Whh_r,
                                xg_r + (size_t)t * B_ * G4, cin,
                                hs + (size_t)t * BH, cs + (size_t)t * BH,
                                (t == 0) ? 1 : 0);
    }

    // 3) init unroll state
    k_h2h<<<(SB * 32 + 255) / 256, 256>>>(hs, hu0);
    cudaMemcpyAsync(cu, cs, sizeof(float) * (size_t)SB * 1024, cudaMemcpyDeviceToDevice, 0);

    // 4) unrolling LSTM: 15 batched fp16 steps (128x128 tiles)
    for (int j = 0; j <= S_; j++) {
        int nact = (15 - j < 14) ? (15 - j) : 14;
        const __half* hin = (j & 1) ? hu1 : hu0;
        __half*       ho  = (j & 1) ? hu0 : hu1;
        int final_t = S_ - j;
        dim3 g(G4 / 128, nact * 2);
        k_mma_lstm<<<g, 256, SMEM_LSTM>>>(hin, whhu, xg_u, cu, ho, cu, hn, final_t);
    }

    // 5) classifier
    {
        dim3 g((C_ + 127) / 128, SB / 128);
        k_mma_lin<0><<<g, 256, SMEM_LIN>>>(hn, wc, out, bc, nullptr, C_);
    }
}